// round 13
// baseline (speedup 1.0000x reference)
#include <cuda_runtime.h>
#include <cuda_bf16.h>
#include <math.h>
#include <stdint.h>

#define N_NODES 16384
#define E_EDGES 147456
#define HD 128
#define NSEG 32
#define SEGSZ 512
#define KEDGE 9
#define EFK 64

#define FLAG_SILU 1
#define FLAG_RESPRE 2
#define FLAG_COMBINE 4

// ---------------- fp32 scratch ----------------
__device__ float g_t0[N_NODES * HD];
__device__ float g_h[N_NODES * HD];
__device__ float g_ArAc[N_NODES * 2 * HD];
__device__ float g_hintra[N_NODES * HD];
__device__ float g_v2n[N_NODES * HD];
__device__ float g_mix[N_NODES * 2 * HD];
__device__ float g_ef[(long)E_EDGES * EFK];
__device__ float g_epre4[(long)4 * E_EDGES * HD];   // per-layer ef@Wef + be1
__device__ float g_mvv[(long)E_EDGES * HD];
__device__ float g_unit[E_EDGES * 3];
__device__ float g_usum[N_NODES * 3];
__device__ float g_va[N_NODES * 3 * HD];
__device__ float g_vb[N_NODES * 3 * HD];
__device__ float g_vagg[N_NODES * 3 * HD];
__device__ float g_vp[(long)N_NODES * 3 * 256];
__device__ float g_w[N_NODES];
__device__ float g_meanp[NSEG * 8 * HD];
__device__ float g_pv[N_NODES * 27];
__device__ float g_pred[NSEG * 27];
// fp32 weight staging
__device__ float g_We1cat[4 * HD * 256];
__device__ float g_Wef[4 * EFK * HD];
__device__ float g_W2v[4 * HD * HD];   // We2 @ Wvv
__device__ float g_MWv[4 * HD * HD];   // We2 @ Wv
__device__ float g_W2h[4 * HD * HD];   // We2 @ Wh1b
__device__ float g_Wgvcat[HD * 256];
__device__ float g_bWv[4 * HD];
__device__ float g_bWvv[4 * HD];
__device__ float g_bh1adj[4 * HD];     // bh1 + 9*be2 @ Wh1b

// ---------------- bf16 split operand buffers ----------------
__device__ __align__(16) __nv_bfloat16 a2_cat[(long)N_NODES * 768];
__device__ __align__(16) __nv_bfloat16 a2_u[(long)N_NODES * 384];
__device__ __align__(16) __nv_bfloat16 a2_x[(long)N_NODES * 384];
__device__ __align__(16) __nv_bfloat16 a2_t[(long)E_EDGES * 384];
__device__ __align__(16) __nv_bfloat16 a2_ef[(long)E_EDGES * 192];
__device__ __align__(16) __nv_bfloat16 a2_M[(long)3 * N_NODES * 384];
__device__ __align__(16) __nv_bfloat16 b2_We1cat[4 * 256 * 384];
__device__ __align__(16) __nv_bfloat16 b2_Wef[4 * 128 * 192];
__device__ __align__(16) __nv_bfloat16 b2_W2v[4 * 128 * 384];
__device__ __align__(16) __nv_bfloat16 b2_MWv[4 * 128 * 384];
__device__ __align__(16) __nv_bfloat16 b2_Wh1[4 * 128 * 768];
__device__ __align__(16) __nv_bfloat16 b2_Wh2[4 * 128 * 384];
__device__ __align__(16) __nv_bfloat16 b2_Wi1[4 * 128 * 384];
__device__ __align__(16) __nv_bfloat16 b2_Wi2[4 * 128 * 384];
__device__ __align__(16) __nv_bfloat16 b2_Wgv[256 * 384];
__device__ __align__(16) __nv_bfloat16 b2_Wg1[128 * 768];
__device__ __align__(16) __nv_bfloat16 b2_Wg2[256 * 384];

// ---------------- helpers ----------------
__device__ __forceinline__ uint32_t smem_to_u32(const void* p) {
    uint32_t a;
    asm("{ .reg .u64 t; cvta.to.shared.u64 t, %1; cvt.u32.u64 %0, t; }" : "=r"(a) : "l"(p));
    return a;
}
__device__ __forceinline__ void wsplit1(__nv_bfloat16* d, int K, float x) {
    __nv_bfloat16 hi = __float2bfloat16(x);
    __nv_bfloat16 lo = __float2bfloat16(x - __bfloat162float(hi));
    d[0] = hi; d[K] = lo; d[2 * K] = hi;
}
#define CP16(dst, src) \
    asm volatile("cp.async.cg.shared.global [%0], [%1], 16;" :: "r"(dst), "l"(src) : "memory")
#define CP_COMMIT() asm volatile("cp.async.commit_group;" ::: "memory")
#define CP_WAIT1()  asm volatile("cp.async.wait_group 1;" ::: "memory")
#define CP_WAIT0()  asm volatile("cp.async.wait_group 0;" ::: "memory")

// ---------------- bf16-split tensor-core GEMM: mma.sync + 3-stage cp.async ----------------
#define SMS 40

template <int BM>
__global__ __launch_bounds__(256, 2)
void tcgemm(const __nv_bfloat16* __restrict__ A2, int lda, int Ktot,
            const __nv_bfloat16* __restrict__ B2,
            const float* __restrict__ bias, const float* __restrict__ res,
            float* __restrict__ C, int Nt, int flags,
            __nv_bfloat16* __restrict__ sdst, int sldd,
            const int* __restrict__ edges, const float* __restrict__ ArAc)
{
    constexpr int AUNITS = BM / 64;
    constexpr int IITER = BM / 32;
    constexpr int SE = (BM + 128) * SMS;

    extern __shared__ __align__(16) char smraw[];
    __nv_bfloat16* sm = (__nv_bfloat16*)smraw;

    const int t = threadIdx.x;
    const int lid = t & 31;
    const int wid = t >> 5;
    const int wm = wid & 1;
    const int wn = wid >> 1;
    const int bm = blockIdx.y * BM;
    const int bn = blockIdx.x * 128;

    float acc[IITER][4][4];
#pragma unroll
    for (int i = 0; i < IITER; i++)
#pragma unroll
        for (int j = 0; j < 4; j++)
#pragma unroll
            for (int r = 0; r < 4; r++) acc[i][j][r] = 0.0f;

    const int r0 = t >> 2;
    const int kq = (t & 3) << 3;

    const int a_row = wm * (BM / 2) + (lid & 7) + ((lid >> 3) & 1) * 8;
    const int a_col = ((lid >> 4) & 1) * 8;
    const int a_off = a_row * SMS + a_col;
    const int b_row = wn * 32 + (lid & 7);
    const int b_col = ((lid >> 3) & 1) * 8;
    const int b_off = b_row * SMS + b_col;

    const int iters = Ktot >> 5;

    long arow[AUNITS];
#pragma unroll
    for (int r = 0; r < AUNITS; r++) arow[r] = (long)(bm + r0 + r * 64) * lda + kq;
    const long brow0 = (long)(bn + r0) * Ktot + kq;
    const long brow1 = (long)(bn + r0 + 64) * Ktot + kq;

#pragma unroll
    for (int p = 0; p < 2; p++) {
        __nv_bfloat16* sA = sm + p * SE;
        __nv_bfloat16* sB = sA + BM * SMS;
        const int k0 = p << 5;
#pragma unroll
        for (int r = 0; r < AUNITS; r++)
            CP16(smem_to_u32(sA + (r0 + r * 64) * SMS + kq), A2 + arow[r] + k0);
        CP16(smem_to_u32(sB + r0 * SMS + kq), B2 + brow0 + k0);
        CP16(smem_to_u32(sB + (r0 + 64) * SMS + kq), B2 + brow1 + k0);
        CP_COMMIT();
    }

    int stage = 0;
    for (int it = 0; it < iters; it++) {
        if (it + 1 < iters) { CP_WAIT1(); } else { CP_WAIT0(); }
        __syncthreads();

        const uint32_t aBase = smem_to_u32(sm + stage * SE);
        const uint32_t bBase = aBase + BM * SMS * 2;
#pragma unroll
        for (int ks = 0; ks < 2; ks++) {
            uint32_t a[IITER][4];
#pragma unroll
            for (int i = 0; i < IITER; i++) {
                const uint32_t addr = aBase + 2u * (a_off + i * 16 * SMS + ks * 16);
                asm volatile(
                    "ldmatrix.sync.aligned.m8n8.x4.shared.b16 {%0,%1,%2,%3}, [%4];"
                    : "=r"(a[i][0]), "=r"(a[i][1]), "=r"(a[i][2]), "=r"(a[i][3])
                    : "r"(addr));
            }
            uint32_t b[4][2];
#pragma unroll
            for (int j = 0; j < 4; j++) {
                const uint32_t addr = bBase + 2u * (b_off + j * 8 * SMS + ks * 16);
                asm volatile(
                    "ldmatrix.sync.aligned.m8n8.x2.shared.b16 {%0,%1}, [%2];"
                    : "=r"(b[j][0]), "=r"(b[j][1])
                    : "r"(addr));
            }
#pragma unroll
            for (int i = 0; i < IITER; i++)
#pragma unroll
                for (int j = 0; j < 4; j++) {
                    asm volatile(
                        "mma.sync.aligned.m16n8k16.row.col.f32.bf16.bf16.f32 "
                        "{%0,%1,%2,%3}, {%4,%5,%6,%7}, {%8,%9}, {%0,%1,%2,%3};"
                        : "+f"(acc[i][j][0]), "+f"(acc[i][j][1]),
                          "+f"(acc[i][j][2]), "+f"(acc[i][j][3])
                        : "r"(a[i][0]), "r"(a[i][1]), "r"(a[i][2]), "r"(a[i][3]),
                          "r"(b[j][0]), "r"(b[j][1]));
                }
        }

        if (it + 2 < iters) {
            __nv_bfloat16* sA = sm + ((stage + 2) % 3) * SE;
            __nv_bfloat16* sB = sA + BM * SMS;
            const int k0 = (it + 2) << 5;
#pragma unroll
            for (int r = 0; r < AUNITS; r++)
                CP16(smem_to_u32(sA + (r0 + r * 64) * SMS + kq), A2 + arow[r] + k0);
            CP16(smem_to_u32(sB + r0 * SMS + kq), B2 + brow0 + k0);
            CP16(smem_to_u32(sB + (r0 + 64) * SMS + kq), B2 + brow1 + k0);
            CP_COMMIT();
        }
        stage = (stage + 1) % 3;
    }

    // epilogue
    const bool f_silu = (flags & FLAG_SILU) != 0;
    const bool f_respre = (flags & FLAG_RESPRE) != 0;
    const bool f_comb = (flags & FLAG_COMBINE) != 0;
    const int g = lid >> 2;
    const int t2 = (lid & 3) << 1;
#pragma unroll
    for (int i = 0; i < IITER; i++) {
#pragma unroll
        for (int half = 0; half < 2; half++) {
            const int m = bm + wm * (BM / 2) + i * 16 + g + half * 8;
            int rrow = 0, ccol = 0;
            if (f_comb) { rrow = m / KEDGE; ccol = edges[E_EDGES + m]; }
#pragma unroll
            for (int j = 0; j < 4; j++) {
                const int n0 = bn + wn * 32 + j * 8 + t2;
                const long base = (long)m * Nt + n0;
                float v0 = acc[i][j][2 * half + 0];
                float v1 = acc[i][j][2 * half + 1];
                if (bias) { v0 += bias[n0]; v1 += bias[n0 + 1]; }
                if (f_comb) {
                    v0 += ArAc[(long)rrow * 256 + n0] + ArAc[(long)ccol * 256 + 128 + n0];
                    v1 += ArAc[(long)rrow * 256 + n0 + 1] + ArAc[(long)ccol * 256 + 128 + n0 + 1];
                }
                if (f_respre && res) { v0 += res[base]; v1 += res[base + 1]; }
                if (f_silu) {
                    v0 = v0 / (1.0f + __expf(-v0));
                    v1 = v1 / (1.0f + __expf(-v1));
                }
                if (!f_respre && res) { v0 += res[base]; v1 += res[base + 1]; }
                if (C) *(float2*)&C[base] = make_float2(v0, v1);
                if (sdst) {
                    __nv_bfloat16 h0 = __float2bfloat16(v0);
                    __nv_bfloat16 h1 = __float2bfloat16(v1);
                    __nv_bfloat16 l0 = __float2bfloat16(v0 - __bfloat162float(h0));
                    __nv_bfloat16 l1 = __float2bfloat16(v1 - __bfloat162float(h1));
                    __nv_bfloat16* d = sdst + (long)m * sldd + n0;
                    __nv_bfloat162 hv; hv.x = h0; hv.y = h1;
                    __nv_bfloat162 lv; lv.x = l0; lv.y = l1;
                    *(__nv_bfloat162*)&d[0] = hv;
                    *(__nv_bfloat162*)&d[Nt] = lv;
                    *(__nv_bfloat162*)&d[2 * Nt] = hv;
                }
            }
        }
    }
}

#define TCSMEM128 (3 * (128 + 128) * SMS * 2)   // 61440 B
#define TCSMEM64  (3 * (64 + 128) * SMS * 2)    // 46080 B

// ---------------- split kernel (fp32 -> [hi|lo|hi]) ----------------
__global__ void splitA_kernel(const float* __restrict__ src, int K,
                              __nv_bfloat16* __restrict__ dst, int ldd, int coff,
                              const float* __restrict__ rowscale, long total)
{
    long idx = (long)blockIdx.x * blockDim.x + threadIdx.x;
    if (idx >= total) return;
    int k = (int)(idx % K);
    long row = idx / K;
    float x = src[idx];
    if (rowscale) x *= rowscale[row];
    wsplit1(dst + row * ldd + coff + k, K, x);
}

// ---------------- edge combine: t = silu(epre + Ar[row] + Ac[col]) -> split ----------------
__global__ void combine_split_kernel(const float* __restrict__ epre,
                                     const float* __restrict__ ArAc,
                                     const int* __restrict__ edges,
                                     __nv_bfloat16* __restrict__ dst)
{
    int e = blockIdx.x;
    int hh = threadIdx.x;
    int r = e / KEDGE;
    int c = edges[E_EDGES + e];
    float x = epre[(long)e * HD + hh] + ArAc[(long)r * 256 + hh] + ArAc[(long)c * 256 + HD + hh];
    x = x / (1.0f + __expf(-x));
    wsplit1(dst + (long)e * 384 + hh, HD, x);
}

// ---------------- fp32 GEMM (initial MLP) ----------------
__device__ __forceinline__ unsigned long long pack2(float lo, float hi) {
    unsigned long long r;
    asm("mov.b64 %0, {%1, %2};" : "=l"(r) : "f"(lo), "f"(hi));
    return r;
}
__device__ __forceinline__ unsigned long long dup2(float v) {
    unsigned long long r;
    asm("mov.b64 %0, {%1, %1};" : "=l"(r) : "f"(v));
    return r;
}
__device__ __forceinline__ void fma2(unsigned long long& acc, unsigned long long a, unsigned long long b) {
    asm("fma.rn.f32x2 %0, %1, %2, %0;" : "+l"(acc) : "l"(a), "l"(b));
}
__device__ __forceinline__ void unpack2(unsigned long long p, float& lo, float& hi) {
    asm("mov.b64 {%0, %1}, %2;" : "=f"(lo), "=f"(hi) : "l"(p));
}

__global__ __launch_bounds__(256, 1)
void gemm128(const float* __restrict__ A, const float* __restrict__ B,
             const float* __restrict__ bias, const float* __restrict__ res,
             float* __restrict__ C, int M, int N, int K, int flags,
             long sA, long sB, long sC)
{
    A += blockIdx.z * sA; B += blockIdx.z * sB; C += blockIdx.z * sC;
    __shared__ float As[2][16][128];
    __shared__ float Bs[2][16][128];
    const int bm = blockIdx.y * 128;
    const int bn = blockIdx.x * 128;
    const int t = threadIdx.x;
    const int ty = t >> 4;
    const int tx = t & 15;

    unsigned long long acc2[8][4];
#pragma unroll
    for (int i = 0; i < 8; i++)
#pragma unroll
        for (int j = 0; j < 4; j++) acc2[i][j] = 0ull;

    const int tiles = K >> 4;
    const int a_row0 = t >> 2;
    const int a_kc = (t & 3) << 2;
    const int b_k0 = t >> 5;
    const int b_n4 = (t & 31) << 2;

    {
#pragma unroll
        for (int r = 0; r < 2; r++) {
            int row = a_row0 + r * 64;
            float4 v = *(const float4*)&A[(long)(bm + row) * K + a_kc];
            As[0][a_kc + 0][row] = v.x; As[0][a_kc + 1][row] = v.y;
            As[0][a_kc + 2][row] = v.z; As[0][a_kc + 3][row] = v.w;
        }
#pragma unroll
        for (int r = 0; r < 2; r++) {
            int k = b_k0 + r * 8;
            *(float4*)&Bs[0][k][b_n4] = *(const float4*)&B[(long)k * N + bn + b_n4];
        }
    }
    __syncthreads();

    for (int tt = 0; tt < tiles; tt++) {
        const int buf = tt & 1;
        float4 pa[2], pb[2];
        if (tt + 1 < tiles) {
            const int k0n = (tt + 1) << 4;
#pragma unroll
            for (int r = 0; r < 2; r++)
                pa[r] = *(const float4*)&A[(long)(bm + a_row0 + r * 64) * K + k0n + a_kc];
#pragma unroll
            for (int r = 0; r < 2; r++)
                pb[r] = *(const float4*)&B[(long)(k0n + b_k0 + r * 8) * N + bn + b_n4];
        }
#pragma unroll
        for (int k = 0; k < 16; k++) {
            float a[8];
            float4 a0 = *(const float4*)&As[buf][k][ty * 8];
            float4 a1 = *(const float4*)&As[buf][k][ty * 8 + 4];
            a[0] = a0.x; a[1] = a0.y; a[2] = a0.z; a[3] = a0.w;
            a[4] = a1.x; a[5] = a1.y; a[6] = a1.z; a[7] = a1.w;
            float4 b0 = *(const float4*)&Bs[buf][k][tx * 8];
            float4 b1 = *(const float4*)&Bs[buf][k][tx * 8 + 4];
            unsigned long long b2[4];
            b2[0] = pack2(b0.x, b0.y); b2[1] = pack2(b0.z, b0.w);
            b2[2] = pack2(b1.x, b1.y); b2[3] = pack2(b1.z, b1.w);
#pragma unroll
            for (int i = 0; i < 8; i++) {
                unsigned long long ad = dup2(a[i]);
#pragma unroll
                for (int j = 0; j < 4; j++) fma2(acc2[i][j], ad, b2[j]);
            }
        }
        if (tt + 1 < tiles) {
            const int nb = buf ^ 1;
#pragma unroll
            for (int r = 0; r < 2; r++) {
                int row = a_row0 + r * 64;
                As[nb][a_kc + 0][row] = pa[r].x; As[nb][a_kc + 1][row] = pa[r].y;
                As[nb][a_kc + 2][row] = pa[r].z; As[nb][a_kc + 3][row] = pa[r].w;
            }
#pragma unroll
            for (int r = 0; r < 2; r++)
                *(float4*)&Bs[nb][b_k0 + r * 8][b_n4] = pb[r];
        }
        __syncthreads();
    }

    const bool silu = (flags & FLAG_SILU) != 0;
#pragma unroll
    for (int i = 0; i < 8; i++) {
        const int m = bm + ty * 8 + i;
        float cv[8];
#pragma unroll
        for (int j = 0; j < 4; j++) unpack2(acc2[i][j], cv[2 * j], cv[2 * j + 1]);
        const long base = (long)m * N + bn + tx * 8;
#pragma unroll
        for (int j = 0; j < 8; j++) {
            float v = cv[j];
            if (bias) v += bias[bn + tx * 8 + j];
            if (silu) v = v / (1.0f + __expf(-v));
            if (res) v += res[base + j];
            cv[j] = v;
        }
        float4* cp = (float4*)&C[base];
        cp[0] = make_float4(cv[0], cv[1], cv[2], cv[3]);
        cp[1] = make_float4(cv[4], cv[5], cv[6], cv[7]);
    }
}

// ---------------- small weight-product kernel: We2 @ {Wvv, Wv, Wh1b} ----------------
__global__ void wprod_kernel(const float* __restrict__ We2, const float* __restrict__ Wv,
                             const float* __restrict__ Wvv, const float* __restrict__ Wh1,
                             float* __restrict__ MWv, float* __restrict__ W2v,
                             float* __restrict__ W2h)
{
    int l = blockIdx.z;
    int row = blockIdx.y;
    int n = threadIdx.x;
    __shared__ float a[HD];
    a[n] = We2[(long)l * HD * HD + row * HD + n];
    __syncthreads();
    const float* B;
    float* O;
    if (blockIdx.x == 0)      { B = Wvv + (long)l * HD * HD;                O = W2v; }
    else if (blockIdx.x == 1) { B = Wv + (long)l * HD * HD;                 O = MWv; }
    else                      { B = Wh1 + (long)l * 256 * HD + 128 * HD;    O = W2h; }
    float s = 0.0f;
#pragma unroll 8
    for (int k = 0; k < HD; k++) s += a[k] * B[k * HD + n];
    O[(long)l * HD * HD + row * HD + n] = s;
}

// ---------------- staging pack kernels (fp32) ----------------
__global__ void pack_We1cat_kernel(const float* __restrict__ We1, float* __restrict__ out)
{
    int idx = blockIdx.x * blockDim.x + threadIdx.x;
    if (idx >= 4 * HD * 256) return;
    int l = idx / (HD * 256);
    int rem = idx - l * HD * 256;
    int k = rem >> 8, n = rem & 255;
    const float* base = We1 + (long)l * 292 * HD;
    out[idx] = (n < HD) ? base[k * HD + n] : base[(HD + k) * HD + (n - HD)];
}
__global__ void pack_Wef_kernel(const float* __restrict__ We1, float* __restrict__ out)
{
    int idx = blockIdx.x * blockDim.x + threadIdx.x;
    if (idx >= 4 * EFK * HD) return;
    int l = idx / (EFK * HD);
    int rem = idx - l * EFK * HD;
    int k = rem >> 7, n = rem & 127;
    out[idx] = (k < 36) ? We1[(long)l * 292 * HD + (256 + k) * HD + n] : 0.0f;
}
__global__ void pack_Wgv_kernel(const float* __restrict__ Wgv1, const float* __restrict__ Wgv2,
                                float* __restrict__ out)
{
    int idx = blockIdx.x * blockDim.x + threadIdx.x;
    if (idx >= HD * 256) return;
    int k = idx >> 8, n = idx & 255;
    out[idx] = (n < HD) ? Wgv1[k * HD + n] : Wgv2[k * HD + (n - HD)];
}
__global__ void bias_pre_kernel(const float* __restrict__ be2, const float* __restrict__ Wv,
                                const float* __restrict__ Wvv, const float* __restrict__ Wh1,
                                const float* __restrict__ bh1,
                                float* __restrict__ bWv, float* __restrict__ bWvv,
                                float* __restrict__ bh1adj)
{
    int l = blockIdx.x;
    int n = threadIdx.x;
    const float* b = be2 + l * HD;
    float s1 = 0.f, s2 = 0.f, s3 = 0.f;
    const float* w1 = Wv + (long)l * HD * HD;
    const float* w2 = Wvv + (long)l * HD * HD;
    const float* w3 = Wh1 + (long)l * 256 * HD + 128 * HD;
#pragma unroll 8
    for (int k = 0; k < HD; k++) {
        s1 += b[k] * w1[k * HD + n];
        s2 += b[k] * w2[k * HD + n];
        s3 += b[k] * w3[k * HD + n];
    }
    bWv[l * HD + n] = s1;
    bWvv[l * HD + n] = s2;
    bh1adj[l * HD + n] = bh1[l * HD + n] + 9.0f * s3;
}

// ---------------- single fused bf16 B-pack ----------------
#define NJOBS 13
struct PackJobs {
    const float* src[NJOBS];
    long sstride[NJOBS];
    long dstride[NJOBS];
    __nv_bfloat16* dst[NJOBS];
    int K[NJOBS];
    int N[NJOBS];
    int ldd[NJOBS];
    int coff[NJOBS];
    int layers[NJOBS];
};
__global__ void pack_all_kernel(PackJobs J)
{
    int j = blockIdx.y;
    int l = blockIdx.z;
    if (l >= J.layers[j]) return;
    int idx = blockIdx.x * 256 + threadIdx.x;
    int KN = J.K[j] * J.N[j];
    if (idx >= KN) return;
    int k = idx / J.N[j], n = idx % J.N[j];
    float x = J.src[j][(long)l * J.sstride[j] + idx];
    __nv_bfloat16 hi = __float2bfloat16(x);
    __nv_bfloat16 lo = __float2bfloat16(x - __bfloat162float(hi));
    __nv_bfloat16* d = J.dst[j] + (long)l * J.dstride[j] + (long)n * J.ldd[j] + J.coff[j];
    d[k] = hi;
    d[J.K[j] + k] = hi;
    d[2 * J.K[j] + k] = lo;
}

// ---------------- elementwise / reduction kernels ----------------
__global__ void edge_geom_kernel(const float* __restrict__ X, const float* __restrict__ edge_attr,
                                 const int* __restrict__ edges,
                                 float* __restrict__ unit, float* __restrict__ ef)
{
    int e = blockIdx.x * blockDim.x + threadIdx.x;
    if (e >= E_EDGES) return;
    int r = edges[e];
    int c = edges[E_EDGES + e];
    float dx = X[r * 3 + 0] - X[c * 3 + 0];
    float dy = X[r * 3 + 1] - X[c * 3 + 1];
    float dz = X[r * 3 + 2] - X[c * 3 + 2];
    float norm = sqrtf(dx * dx + dy * dy + dz * dz) + 1e-8f;
    float invn = 1.0f / norm;
    unit[e * 3 + 0] = dx * invn;
    unit[e * 3 + 1] = dy * invn;
    unit[e * 3 + 2] = dz * invn;
    const float PI_ = 3.14159265358979323846f;
    float cn = fminf(norm, 1.0f);
    float cut = 0.5f * (cosf(PI_ * cn) + 1.0f);
    float f = cut * invn;
#pragma unroll
    for (int j = 0; j < 20; j++)
        ef[(long)e * EFK + j] = sinf(norm * PI_ * (float)(j + 1)) * f;
#pragma unroll
    for (int j = 0; j < 16; j++)
        ef[(long)e * EFK + 20 + j] = edge_attr[e * 16 + j];
#pragma unroll
    for (int j = 36; j < EFK; j++)
        ef[(long)e * EFK + j] = 0.0f;
}

__global__ void aggT_kernel(const __nv_bfloat16* __restrict__ t2, const float* __restrict__ unit,
                            __nv_bfloat16* __restrict__ aggdst, int aggld,
                            __nv_bfloat16* __restrict__ Mdst, float* __restrict__ usum)
{
    int n = blockIdx.x;
    int hh = threadIdx.x;
    float s = 0.f, mx = 0.f, my = 0.f, mz = 0.f;
#pragma unroll
    for (int j = 0; j < KEDGE; j++) {
        long e = (long)n * KEDGE + j;
        float tt = __bfloat162float(t2[e * 384 + hh]) + __bfloat162float(t2[e * 384 + 128 + hh]);
        float ux = unit[e * 3 + 0];
        float uy = unit[e * 3 + 1];
        float uz = unit[e * 3 + 2];
        s += tt; mx += tt * ux; my += tt * uy; mz += tt * uz;
    }
    wsplit1(aggdst + (long)n * aggld + hh, 128, s);
    wsplit1(Mdst + (long)(3 * n + 0) * 384 + hh, 128, mx);
    wsplit1(Mdst + (long)(3 * n + 1) * 384 + hh, 128, my);
    wsplit1(Mdst + (long)(3 * n + 2) * 384 + hh, 128, mz);
    if (hh < 3) {
        float u = 0.f;
#pragma unroll
        for (int j = 0; j < KEDGE; j++) u += unit[((long)n * KEDGE + j) * 3 + hh];
        usum[n * 3 + hh] = u;
    }
}

__global__ void vupdate_kernel(const float* __restrict__ vin, float* __restrict__ vout,
                               const float* __restrict__ mvv, const float* __restrict__ vagg,
                               const float* __restrict__ usum, const float* __restrict__ bWv,
                               const int* __restrict__ edges)
{
    int n = blockIdx.x;
    int hh = threadIdx.x;
    float bw = bWv[hh];
    float a0 = vagg[(long)n * 384 + hh]       + usum[n * 3 + 0] * bw;
    float a1 = vagg[(long)n * 384 + 128 + hh] + usum[n * 3 + 1] * bw;
    float a2 = vagg[(long)n * 384 + 256 + hh] + usum[n * 3 + 2] * bw;
    if (vin) {
        a0 += vin[(long)n * 384 + hh];
        a1 += vin[(long)n * 384 + 128 + hh];
        a2 += vin[(long)n * 384 + 256 + hh];
#pragma unroll
        for (int j = 0; j < KEDGE; j++) {
            long e = (long)n * KEDGE + j;
            int c = edges[E_EDGES + e];
            float b = mvv[e * HD + hh];
            a0 += b * vin[(long)c * 384 + hh];
            a1 += b * vin[(long)c * 384 + 128 + hh];
            a2 += b * vin[(long)c * 384 + 256 + hh];
        }
    }
    vout[(long)n * 384 + hh] = a0;
    vout[(long)n * 384 + 128 + hh] = a1;
    vout[(long)n * 384 + 256 + hh] = a2;
}

__global__ void meanh1_kernel(const float* __restrict__ hintra, float* __restrict__ part)
{
    int s = blockIdx.x;
    int c = blockIdx.y;
    int k = threadIdx.x;
    float acc = 0.0f;
    const float* p = hintra + ((long)s * SEGSZ + c * 64) * HD + k;
#pragma unroll 8
    for (int u = 0; u < 64; u++) acc += p[u * HD];
    part[(s * 8 + c) * HD + k] = acc;
}

// attn: reads 8-way partials of opposite segment directly (meanh2 fused)
__global__ void attn_kernel(const float* __restrict__ hintra, const float* __restrict__ part,
                            float* __restrict__ w)
{
    int s = blockIdx.x;
    int t = threadIdx.x;
    __shared__ float sm[HD];
    __shared__ float red[SEGSZ];
    int opp = s ^ 1;
    if (t < HD) {
        float a = 0.0f;
#pragma unroll
        for (int c = 0; c < 8; c++) a += part[(opp * 8 + c) * HD + t];
        sm[t] = a * (1.0f / (float)SEGSZ);
    }
    __syncthreads();
    int node = s * SEGSZ + t;
    const float* hr = hintra + (long)node * HD;
    float sc = 0.0f;
#pragma unroll 8
    for (int k = 0; k < HD; k++) sc += hr[k] * sm[k];
    red[t] = sc;
    __syncthreads();
    for (int st = SEGSZ / 2; st > 0; st >>= 1) {
        if (t < st) red[t] = fmaxf(red[t], red[t + st]);
        __syncthreads();
    }
    float mx = red[0];
    __syncthreads();
    float ex = expf(sc - mx);
    red[t] = ex;
    __syncthreads();
    for (int st = SEGSZ / 2; st > 0; st >>= 1) {
        if (t < st) red[t] += red[t + st];
        __syncthreads();
    }
    w[node] = ex / red[0];
}

__global__ void v2n_kernel(const float* __restrict__ vp, float* __restrict__ v2n)
{
    int idx = blockIdx.x * blockDim.x + threadIdx.x;
    if (idx >= N_NODES * HD) return;
    int n = idx / HD;
    int k = idx % HD;
    float a = vp[(long)(n * 3 + 0) * 256 + HD + k];
    float b = vp[(long)(n * 3 + 1) * 256 + HD + k];
    float c = vp[(long)(n * 3 + 2) * 256 + HD + k];
    v2n[idx] = sqrtf(a * a + b * b + c * c + 1e-8f);
}

__global__ void pv_kernel(const float* __restrict__ vp, const float* __restrict__ mix,
                          const float* __restrict__ Wf, float* __restrict__ pv)
{
    int n = blockIdx.x;
    int k = threadIdx.x;
    __shared__ float sd[3][HD];
    float hf = mix[(long)n * 256 + k];
    float bg = mix[(long)n * 256 + HD + k];
    float s = hf * bg;
    sd[0][k] = vp[(long)(n * 3 + 0) * 256 + k] * s;
    sd[1][k] = vp[(long)(n * 3 + 1) * 256 + k] * s;
    sd[2][k] = vp[(long)(n * 3 + 2) * 256 + k] * s;
    __syncthreads();
    if (k < 27) {
        int o = k / 3, c = k % 3;
        float acc = 0.0f;
#pragma unroll 8
        for (int kk = 0; kk < HD; kk++) acc += sd[c][kk] * Wf[kk * 9 + o];
        pv[(long)n * 27 + k] = acc;
    }
}

__global__ void predsum_kernel(const float* __restrict__ pv, float* __restrict__ pred)
{
    int s = blockIdx.x;
    int j = threadIdx.x;
    if (j >= 27) return;
    float acc = 0.0f;
    for (int u = 0; u < SEGSZ; u++)
        acc += pv[(long)(s * SEGSZ + u) * 27 + j];
    pred[s * 27 + j] = acc;
}

__global__ void final_kernel(const float* __restrict__ pred, float* __restrict__ out)
{
    int s = threadIdx.x;
    if (s >= NSEG) return;
    const float* p = pred + s * 27;
#pragma unroll
    for (int r = 0; r < 3; r++) {
#pragma unroll
        for (int c = 0; c < 3; c++) {
            float A = p[0 * 3 + r] * p[1 * 3 + c]
                    + p[3 * 3 + r] * p[2 * 3 + c]
                    + p[4 * 3 + r] * p[5 * 3 + c]
                    + p[7 * 3 + r] * p[6 * 3 + c];
            out[s * 12 + r * 4 + c] = A * 100.0f;
        }
        out[s * 12 + r * 4 + 3] = p[8 * 3 + r] * 10.0f;
    }
}

// ---------------- host driver ----------------
static void launch_tc(const __nv_bfloat16* A2, int lda, int Ktot, const __nv_bfloat16* B2,
                      const float* bias, const float* res, float* C, int M, int Nt, int flags,
                      __nv_bfloat16* sdst = nullptr, int sldd = 0,
                      const int* edges = nullptr, const float* ArAc = nullptr,
                      int bmtile = 128, cudaStream_t st = 0)
{
    if (bmtile == 64) {
        dim3 grid(Nt / 128, M / 64);
        tcgemm<64><<<grid, 256, TCSMEM64, st>>>(A2, lda, Ktot, B2, bias, res, C, Nt, flags,
                                                sdst, sldd, edges, ArAc);
    } else {
        dim3 grid(Nt / 128, M / 128);
        tcgemm<128><<<grid, 256, TCSMEM128, st>>>(A2, lda, Ktot, B2, bias, res, C, Nt, flags,
                                                  sdst, sldd, edges, ArAc);
    }
}

static void launch_gemm(const float* A, const float* B, const float* bias,
                        const float* res, float* C, int M, int N, int K, int flags,
                        int batch = 1, long sA = 0, long sB = 0, long sC = 0)
{
    dim3 grid(N / 128, M / 128, batch);
    gemm128<<<grid, 256>>>(A, B, bias, res, C, M, N, K, flags, sA, sB, sC);
}

static void launch_split(const float* src, int M, int K, __nv_bfloat16* dst, int ldd, int coff,
                         const float* rowscale)
{
    long total = (long)M * K;
    splitA_kernel<<<(int)((total + 255) / 256), 256>>>(src, K, dst, ldd, coff, rowscale, total);
}

template <typename T>
static T* sym(const void* s)
{
    void* p = nullptr;
    cudaGetSymbolAddress(&p, s);
    return (T*)p;
}

extern "C" void kernel_launch(void* const* d_in, const int* in_sizes, int n_in,
                              void* d_out, int out_size)
{
    const float* X        = (const float*)d_in[0];
    const float* node_attr= (const float*)d_in[1];
    const float* edge_attr= (const float*)d_in[2];
    const float* W_in1    = (const float*)d_in[3];
    const float* b_in1    = (const float*)d_in[4];
    const float* W_in2    = (const float*)d_in[5];
    const float* b_in2    = (const float*)d_in[6];
    const float* We1      = (const float*)d_in[7];
    const float* be1      = (const float*)d_in[8];
    const float* We2      = (const float*)d_in[9];
    const float* be2      = (const float*)d_in[10];
    const float* Wv       = (const float*)d_in[11];
    const float* Wvv      = (const float*)d_in[12];
    const float* Wh1      = (const float*)d_in[13];
    const float* bh1      = (const float*)d_in[14];
    const float* Wh2      = (const float*)d_in[15];
    const float* bh2      = (const float*)d_in[16];
    const float* Wi1      = (const float*)d_in[17];
    const float* bi1      = (const float*)d_in[18];
    const float* Wi2      = (const float*)d_in[19];
    const float* bi2      = (const float*)d_in[20];
    const float* Wgv1     = (const float*)d_in[21];
    const float* Wgv2     = (const float*)d_in[22];
    const float* Wg1      = (const float*)d_in[23];
    const float* bg1      = (const float*)d_in[24];
    const float* Wg2      = (const float*)d_in[25];
    const float* bg2      = (const float*)d_in[26];
    const float* Wf       = (const float*)d_in[27];
    const int*   edges    = (const int*)d_in[28];
    float* out = (float*)d_out;

    static bool attr_done = false;
    static cudaStream_t s2, s3;
    static cudaEvent_t evT, evAgg, evV, evSetup, evE[4];
    if (!attr_done) {
        cudaFuncSetAttribute(tcgemm<128>, cudaFuncAttributeMaxDynamicSharedMemorySize, TCSMEM128);
        cudaFuncSetAttribute(tcgemm<64>, cudaFuncAttributeMaxDynamicSharedMemorySize, TCSMEM64);
        cudaStreamCreateWithFlags(&s2, cudaStreamNonBlocking);
        cudaStreamCreateWithFlags(&s3, cudaStreamNonBlocking);
        cudaEventCreateWithFlags(&evT, cudaEventDisableTiming);
        cudaEventCreateWithFlags(&evAgg, cudaEventDisableTiming);
        cudaEventCreateWithFlags(&evV, cudaEventDisableTiming);
        cudaEventCreateWithFlags(&evSetup, cudaEventDisableTiming);
        for (int i = 0; i < 4; i++)
            cudaEventCreateWithFlags(&evE[i], cudaEventDisableTiming);
        attr_done = true;
    }

    float* p_t0     = sym<float>(g_t0);
    float* p_h      = sym<float>(g_h);
    float* p_ArAc   = sym<float>(g_ArAc);
    float* p_hintra = sym<float>(g_hintra);
    float* p_v2n    = sym<float>(g_v2n);
    float* p_mix    = sym<float>(g_mix);
    float* p_ef     = sym<float>(g_ef);
    float* p_epre4  = sym<float>(g_epre4);
    float* p_mvv    = sym<float>(g_mvv);
    float* p_unit   = sym<float>(g_unit);
    float* p_usum   = sym<float>(g_usum);
    float* p_va     = sym<float>(g_va);
    float* p_vb     = sym<float>(g_vb);
    float* p_vagg   = sym<float>(g_vagg);
    float* p_vp     = sym<float>(g_vp);
    float* p_w      = sym<float>(g_w);
    float* p_meanp  = sym<float>(g_meanp);
    float* p_pv     = sym<float>(g_pv);
    float* p_pred   = sym<float>(g_pred);
    float* p_We1cat = sym<float>(g_We1cat);
    float* p_Wef    = sym<float>(g_Wef);
    float* p_W2v    = sym<float>(g_W2v);
    float* p_MWv    = sym<float>(g_MWv);
    float* p_W2h    = sym<float>(g_W2h);
    float* p_Wgvcat = sym<float>(g_Wgvcat);
    float* p_bWv    = sym<float>(g_bWv);
    float* p_bWvv   = sym<float>(g_bWvv);
    float* p_bh1adj = sym<float>(g_bh1adj);

    __nv_bfloat16* pa_cat = sym<__nv_bfloat16>(a2_cat);
    __nv_bfloat16* pa_u   = sym<__nv_bfloat16>(a2_u);
    __nv_bfloat16* pa_x   = sym<__nv_bfloat16>(a2_x);
    __nv_bfloat16* pa_t   = sym<__nv_bfloat16>(a2_t);
    __nv_bfloat16* pa_ef  = sym<__nv_bfloat16>(a2_ef);
    __nv_bfloat16* pa_M   = sym<__nv_bfloat16>(a2_M);
    __nv_bfloat16* pb_We1 = sym<__nv_bfloat16>(b2_We1cat);
    __nv_bfloat16* pb_Wef = sym<__nv_bfloat16>(b2_Wef);
    __nv_bfloat16* pb_W2v = sym<__nv_bfloat16>(b2_W2v);
    __nv_bfloat16* pb_MWv = sym<__nv_bfloat16>(b2_MWv);
    __nv_bfloat16* pb_Wh1 = sym<__nv_bfloat16>(b2_Wh1);
    __nv_bfloat16* pb_Wh2 = sym<__nv_bfloat16>(b2_Wh2);
    __nv_bfloat16* pb_Wi1 = sym<__nv_bfloat16>(b2_Wi1);
    __nv_bfloat16* pb_Wi2 = sym<__nv_bfloat16>(b2_Wi2);
    __nv_bfloat16* pb_Wgv = sym<__nv_bfloat16>(b2_Wgv);
    __nv_bfloat16* pb_Wg1 = sym<__nv_bfloat16>(b2_Wg1);
    __nv_bfloat16* pb_Wg2 = sym<__nv_bfloat16>(b2_Wg2);

    // ---- weight staging ----
    pack_We1cat_kernel<<<(4 * HD * 256 + 255) / 256, 256>>>(We1, p_We1cat);
    pack_Wef_kernel<<<(4 * EFK * HD + 255) / 256, 256>>>(We1, p_Wef);
    pack_Wgv_kernel<<<(HD * 256 + 255) / 256, 256>>>(Wgv1, Wgv2, p_Wgvcat);
    {
        dim3 g(3, HD, 4);
        wprod_kernel<<<g, HD>>>(We2, Wv, Wvv, Wh1, p_MWv, p_W2v, p_W2h);
    }
    bias_pre_kernel<<<4, HD>>>(be2, Wv, Wvv, Wh1, bh1, p_bWv, p_bWvv, p_bh1adj);

    // ---- single fused bf16 B-pack ----
    {
        PackJobs J;
        auto set = [&](int j, const float* src, long ss, int K, int N,
                       __nv_bfloat16* dst, long ds, int ldd, int coff, int layers) {
            J.src[j] = src; J.sstride[j] = ss; J.K[j] = K; J.N[j] = N;
            J.dst[j] = dst; J.dstride[j] = ds; J.ldd[j] = ldd; J.coff[j] = coff;
            J.layers[j] = layers;
        };
        set(0,  p_We1cat, (long)HD * 256, 128, 256, pb_We1, (long)256 * 384, 384, 0, 4);
        set(1,  p_Wef, (long)EFK * HD, 64, 128, pb_Wef, (long)128 * 192, 192, 0, 4);
        set(2,  p_W2v, (long)HD * HD, 128, 128, pb_W2v, (long)128 * 384, 384, 0, 4);
        set(3,  p_MWv, (long)HD * HD, 128, 128, pb_MWv, (long)128 * 384, 384, 0, 4);
        set(4,  p_W2h, (long)HD * HD, 128, 128, pb_Wh1, (long)128 * 768, 768, 384, 4);
        set(5,  Wh1, (long)256 * HD, 128, 128, pb_Wh1, (long)128 * 768, 768, 0, 4);
        set(6,  Wh2, (long)HD * HD, 128, 128, pb_Wh2, (long)128 * 384, 384, 0, 4);
        set(7,  Wi1, (long)HD * HD, 128, 128, pb_Wi1, (long)128 * 384, 384, 0, 4);
        set(8,  Wi2, (long)HD * HD, 128, 128, pb_Wi2, (long)128 * 384, 384, 0, 4);
        set(9,  p_Wgvcat, 0, 128, 256, pb_Wgv, 0, 384, 0, 1);
        set(10, Wg1, 0, 128, 128, pb_Wg1, 0, 768, 0, 1);
        set(11, Wg1 + 128 * HD, 0, 128, 128, pb_Wg1, 0, 768, 384, 1);
        set(12, Wg2, 0, 128, 256, pb_Wg2, 0, 384, 0, 1);
        dim3 grid(128, NJOBS, 4);
        pack_all_kernel<<<grid, 256>>>(J);
    }

    // edge geometry + split ef
    edge_geom_kernel<<<(E_EDGES + 255) / 256, 256>>>(X, edge_attr, edges, p_unit, p_ef);
    launch_split(p_ef, E_EDGES, 64, pa_ef, 192, 0, nullptr);
    cudaEventRecord(evSetup, 0);

    // ---- s3: precompute all 4 epre_i = ef @ Wef_i + be1_i (static across layers) ----
    cudaStreamWaitEvent(s3, evSetup, 0);
    for (int i = 0; i < 4; i++) {
        launch_tc(pa_ef, 192, 192, pb_Wef + (long)i * 128 * 192,
                  be1 + i * HD, nullptr, p_epre4 + (long)i * E_EDGES * HD, E_EDGES, 128, 0,
                  nullptr, 0, nullptr, nullptr, 128, s3);
        cudaEventRecord(evE[i], s3);
    }

    // h = silu(node_attr @ W_in1 + b_in1) @ W_in2 + b_in2  (fp32), split into pa_cat[0:384]
    launch_gemm(node_attr, W_in1, b_in1, nullptr, p_t0, N_NODES, HD, 64, FLAG_SILU);
    launch_gemm(p_t0, W_in2, b_in2, nullptr, p_h, N_NODES, HD, HD, 0);
    launch_split(p_h, N_NODES, HD, pa_cat, 768, 0, nullptr);

    float* vin = nullptr;
    float* vbuf0 = p_va;
    float* vbuf1 = p_vb;

    for (int i = 0; i < 4; i++) {
        const float* bh2_i = bh2 + i * HD;
        const float* bi1_i = bi1 + i * HD;
        const float* bi2_i = bi2 + i * HD;
        float* vout = (i & 1) ? vbuf1 : vbuf0;

        // [Ar|Ac] = h @ [W_r|W_c]
        launch_tc(pa_cat, 768, 384, pb_We1 + (long)i * 256 * 384,
                  nullptr, nullptr, p_ArAc, N_NODES, 256, 0);

        // protect pa_t / pa_M / p_usum: previous layer's v-chain must be done
        if (i > 0) cudaStreamWaitEvent(0, evV, 0);
        // epre_i must be ready
        cudaStreamWaitEvent(0, evE[i], 0);

        // t = silu(epre_i + Ar[row] + Ac[col]) -> split pa_t (elementwise)
        combine_split_kernel<<<E_EDGES, HD>>>(p_epre4 + (long)i * E_EDGES * HD,
                                              p_ArAc, edges, pa_t);
        cudaEventRecord(evT, 0);

        // ---- v-chain forked to s2 ----
        cudaStreamWaitEvent(s2, evT, 0);
        if (i > 0)
            launch_tc(pa_t, 384, 384, pb_W2v + (long)i * 128 * 384,
                      p_bWvv + i * HD, nullptr, p_mvv, E_EDGES, 128, 0,
                      nullptr, 0, nullptr, nullptr, 128, s2);

        // aggregate t (main)
        aggT_kernel<<<N_NODES, HD>>>(pa_t, p_unit, pa_cat + 384, 768, pa_M, p_usum);
        cudaEventRecord(evAgg, 0);

        // s2: vagg = Mt @ (We2@Wv), then vupdate
        cudaStreamWaitEvent(s2, evAgg, 0);
        launch_tc(pa_M, 384, 384, pb_MWv + (long)i * 128 * 384,
                  nullptr, nullptr, p_vagg, 3 * N_NODES, 128, 0,
                  nullptr, 0, nullptr, nullptr, 128, s2);
        vupdate_kernel<<<N_NODES, HD, 0, s2>>>(vin, vout, p_mvv, p_vagg, p_usum,
                                               p_bWv + i * HD, edges);
        cudaEventRecord(evV, s2);

        // ---- h-chain on main ----
        launch_tc(pa_cat, 768, 768, pb_Wh1 + (long)i * 128 * 768,
                  p_bh1adj + i * HD, nullptr, nullptr, N_NODES, 128, FLAG_SILU, pa_u, 384,
                  nullptr, nullptr, 64);
        launch_tc(pa_u, 384, 384, pb_Wh2 + (long)i * 128 * 384,
                  bh2_i, p_h, p_hintra, N_NODES, 128, 0, nullptr, 0,
                  nullptr, nullptr, 64);

        // segment attention (meanh2 fused into attn)
        {
            dim3 g1(NSEG, 8);
            meanh1_kernel<<<g1, HD>>>(p_hintra, p_meanp);
        }
        attn_kernel<<<NSEG, SEGSZ>>>(p_hintra, p_meanp, p_w);
        launch_split(p_hintra, N_NODES, HD, pa_x, 384, 0, p_w);
        launch_tc(pa_x, 384, 384, pb_Wi1 + (long)i * 128 * 384,
                  bi1_i, nullptr, nullptr, N_NODES, 128, FLAG_SILU, pa_u, 384,
                  nullptr, nullptr, 64);
        launch_tc(pa_u, 384, 384, pb_Wi2 + (long)i * 128 * 384,
                  bi2_i, p_hintra, p_h, N_NODES, 128, 0, pa_cat, 768,
                  nullptr, nullptr, 64);

        vin = vout;
    }

    // join v-chain before final v projection
    cudaStreamWaitEvent(0, evV, 0);

    // [v1 | v2] = v @ [Wgv1 | Wgv2]
    launch_split(vin, 3 * N_NODES, HD, pa_M, 384, 0, nullptr);
    launch_tc(pa_M, 384, 384, pb_Wgv, nullptr, nullptr, p_vp, 3 * N_NODES, 256, 0);
    v2n_kernel<<<(N_NODES * HD + 255) / 256, 256>>>(p_vp, p_v2n);

    // mix = silu([h|v2n] @ Wg1 + bg1) @ Wg2 + bg2
    launch_split(p_v2n, N_NODES, HD, pa_cat, 768, 384, nullptr);
    launch_tc(pa_cat, 768, 768, pb_Wg1, bg1, nullptr, nullptr, N_NODES, 128, FLAG_SILU,
              pa_u, 384, nullptr, nullptr, 64);
    launch_tc(pa_u, 384, 384, pb_Wg2, bg2, nullptr, p_mix, N_NODES, 256, 0,
              nullptr, 0, nullptr, nullptr, 64);

    // epilogue
    pv_kernel<<<N_NODES, HD>>>(p_vp, p_mix, Wf, p_pv);
    predsum_kernel<<<NSEG, 32>>>(p_pv, p_pred);
    final_kernel<<<1, 32>>>(p_pred, out);
}

// round 14
// speedup vs baseline: 1.0321x; 1.0321x over previous
#include <cuda_runtime.h>
#include <cuda_bf16.h>
#include <math.h>
#include <stdint.h>

#define N_NODES 16384
#define E_EDGES 147456
#define HD 128
#define NSEG 32
#define SEGSZ 512
#define KEDGE 9
#define EFK 64
#define EFR 36   // real ef feature count

#define FLAG_SILU 1
#define FLAG_RESPRE 2
#define FLAG_COMBINE 4

// ---------------- fp32 scratch ----------------
__device__ float g_t0[N_NODES * HD];
__device__ float g_h[N_NODES * HD];
__device__ float g_ArAc[N_NODES * 2 * HD];
__device__ float g_hintra[N_NODES * HD];
__device__ float g_v2n[N_NODES * HD];
__device__ float g_mix[N_NODES * 2 * HD];
__device__ float g_ef[(long)E_EDGES * EFK];
__device__ float g_mvv[(long)E_EDGES * HD];
__device__ float g_unit[E_EDGES * 3];
__device__ float g_usum[N_NODES * 3];
__device__ float g_va[N_NODES * 3 * HD];
__device__ float g_vb[N_NODES * 3 * HD];
__device__ float g_vagg[N_NODES * 3 * HD];
__device__ float g_vp[(long)N_NODES * 3 * 256];
__device__ float g_w[N_NODES];
__device__ float g_meanp[NSEG * 8 * HD];
__device__ float g_pv[N_NODES * 27];
__device__ float g_pred[NSEG * 27];
// fp32 weight staging
__device__ float g_We1cat[4 * HD * 256];
__device__ float g_Wef[4 * EFK * HD];
__device__ float g_W2v[4 * HD * HD];   // We2 @ Wvv
__device__ float g_MWv[4 * HD * HD];   // We2 @ Wv
__device__ float g_W2h[4 * HD * HD];   // We2 @ Wh1b
__device__ float g_Wgvcat[HD * 256];
__device__ float g_bWv[4 * HD];
__device__ float g_bWvv[4 * HD];
__device__ float g_bh1adj[4 * HD];     // bh1 + 9*be2 @ Wh1b

// ---------------- bf16 split operand buffers (zero-initialized device globals) ----------------
__device__ __align__(16) __nv_bfloat16 a2_cat[(long)N_NODES * 768];
__device__ __align__(16) __nv_bfloat16 a2_u[(long)N_NODES * 384];
__device__ __align__(16) __nv_bfloat16 a2_x[(long)N_NODES * 384];
__device__ __align__(16) __nv_bfloat16 a2_t[(long)E_EDGES * 384];
__device__ __align__(16) __nv_bfloat16 a2_ef[(long)E_EDGES * 128];   // [hi36|lo36|hi36|pad]
__device__ __align__(16) __nv_bfloat16 a2_M[(long)3 * N_NODES * 384];
__device__ __align__(16) __nv_bfloat16 b2_We1cat[4 * 256 * 384];
__device__ __align__(16) __nv_bfloat16 b2_Wef[4 * 128 * 128];        // [hi36|hi36|lo36|pad]
__device__ __align__(16) __nv_bfloat16 b2_W2v[4 * 128 * 384];
__device__ __align__(16) __nv_bfloat16 b2_MWv[4 * 128 * 384];
__device__ __align__(16) __nv_bfloat16 b2_Wh1[4 * 128 * 768];
__device__ __align__(16) __nv_bfloat16 b2_Wh2[4 * 128 * 384];
__device__ __align__(16) __nv_bfloat16 b2_Wi1[4 * 128 * 384];
__device__ __align__(16) __nv_bfloat16 b2_Wi2[4 * 128 * 384];
__device__ __align__(16) __nv_bfloat16 b2_Wgv[256 * 384];
__device__ __align__(16) __nv_bfloat16 b2_Wg1[128 * 768];
__device__ __align__(16) __nv_bfloat16 b2_Wg2[256 * 384];

// ---------------- helpers ----------------
__device__ __forceinline__ uint32_t smem_to_u32(const void* p) {
    uint32_t a;
    asm("{ .reg .u64 t; cvta.to.shared.u64 t, %1; cvt.u32.u64 %0, t; }" : "=r"(a) : "l"(p));
    return a;
}
__device__ __forceinline__ void wsplit1(__nv_bfloat16* d, int K, float x) {
    __nv_bfloat16 hi = __float2bfloat16(x);
    __nv_bfloat16 lo = __float2bfloat16(x - __bfloat162float(hi));
    d[0] = hi; d[K] = lo; d[2 * K] = hi;
}
#define CP16(dst, src) \
    asm volatile("cp.async.cg.shared.global [%0], [%1], 16;" :: "r"(dst), "l"(src) : "memory")
#define CP_COMMIT() asm volatile("cp.async.commit_group;" ::: "memory")
#define CP_WAIT1()  asm volatile("cp.async.wait_group 1;" ::: "memory")
#define CP_WAIT0()  asm volatile("cp.async.wait_group 0;" ::: "memory")

// ---------------- bf16-split tensor-core GEMM: mma.sync + 3-stage cp.async ----------------
#define SMS 40

template <int BM>
__global__ __launch_bounds__(256, 2)
void tcgemm(const __nv_bfloat16* __restrict__ A2, int lda, int Ktot,
            const __nv_bfloat16* __restrict__ B2,
            const float* __restrict__ bias, const float* __restrict__ res,
            float* __restrict__ C, int Nt, int flags,
            __nv_bfloat16* __restrict__ sdst, int sldd,
            const int* __restrict__ edges, const float* __restrict__ ArAc)
{
    constexpr int AUNITS = BM / 64;
    constexpr int IITER = BM / 32;
    constexpr int SE = (BM + 128) * SMS;

    extern __shared__ __align__(16) char smraw[];
    __nv_bfloat16* sm = (__nv_bfloat16*)smraw;

    const int t = threadIdx.x;
    const int lid = t & 31;
    const int wid = t >> 5;
    const int wm = wid & 1;
    const int wn = wid >> 1;
    const int bm = blockIdx.y * BM;
    const int bn = blockIdx.x * 128;

    float acc[IITER][4][4];
#pragma unroll
    for (int i = 0; i < IITER; i++)
#pragma unroll
        for (int j = 0; j < 4; j++)
#pragma unroll
            for (int r = 0; r < 4; r++) acc[i][j][r] = 0.0f;

    const int r0 = t >> 2;
    const int kq = (t & 3) << 3;

    const int a_row = wm * (BM / 2) + (lid & 7) + ((lid >> 3) & 1) * 8;
    const int a_col = ((lid >> 4) & 1) * 8;
    const int a_off = a_row * SMS + a_col;
    const int b_row = wn * 32 + (lid & 7);
    const int b_col = ((lid >> 3) & 1) * 8;
    const int b_off = b_row * SMS + b_col;

    const int iters = Ktot >> 5;

    long arow[AUNITS];
#pragma unroll
    for (int r = 0; r < AUNITS; r++) arow[r] = (long)(bm + r0 + r * 64) * lda + kq;
    const long brow0 = (long)(bn + r0) * Ktot + kq;
    const long brow1 = (long)(bn + r0 + 64) * Ktot + kq;

#pragma unroll
    for (int p = 0; p < 2; p++) {
        __nv_bfloat16* sA = sm + p * SE;
        __nv_bfloat16* sB = sA + BM * SMS;
        const int k0 = p << 5;
#pragma unroll
        for (int r = 0; r < AUNITS; r++)
            CP16(smem_to_u32(sA + (r0 + r * 64) * SMS + kq), A2 + arow[r] + k0);
        CP16(smem_to_u32(sB + r0 * SMS + kq), B2 + brow0 + k0);
        CP16(smem_to_u32(sB + (r0 + 64) * SMS + kq), B2 + brow1 + k0);
        CP_COMMIT();
    }

    int stage = 0;
    for (int it = 0; it < iters; it++) {
        if (it + 1 < iters) { CP_WAIT1(); } else { CP_WAIT0(); }
        __syncthreads();

        const uint32_t aBase = smem_to_u32(sm + stage * SE);
        const uint32_t bBase = aBase + BM * SMS * 2;
#pragma unroll
        for (int ks = 0; ks < 2; ks++) {
            uint32_t a[IITER][4];
#pragma unroll
            for (int i = 0; i < IITER; i++) {
                const uint32_t addr = aBase + 2u * (a_off + i * 16 * SMS + ks * 16);
                asm volatile(
                    "ldmatrix.sync.aligned.m8n8.x4.shared.b16 {%0,%1,%2,%3}, [%4];"
                    : "=r"(a[i][0]), "=r"(a[i][1]), "=r"(a[i][2]), "=r"(a[i][3])
                    : "r"(addr));
            }
            uint32_t b[4][2];
#pragma unroll
            for (int j = 0; j < 4; j++) {
                const uint32_t addr = bBase + 2u * (b_off + j * 8 * SMS + ks * 16);
                asm volatile(
                    "ldmatrix.sync.aligned.m8n8.x2.shared.b16 {%0,%1}, [%2];"
                    : "=r"(b[j][0]), "=r"(b[j][1])
                    : "r"(addr));
            }
#pragma unroll
            for (int i = 0; i < IITER; i++)
#pragma unroll
                for (int j = 0; j < 4; j++) {
                    asm volatile(
                        "mma.sync.aligned.m16n8k16.row.col.f32.bf16.bf16.f32 "
                        "{%0,%1,%2,%3}, {%4,%5,%6,%7}, {%8,%9}, {%0,%1,%2,%3};"
                        : "+f"(acc[i][j][0]), "+f"(acc[i][j][1]),
                          "+f"(acc[i][j][2]), "+f"(acc[i][j][3])
                        : "r"(a[i][0]), "r"(a[i][1]), "r"(a[i][2]), "r"(a[i][3]),
                          "r"(b[j][0]), "r"(b[j][1]));
                }
        }

        if (it + 2 < iters) {
            __nv_bfloat16* sA = sm + ((stage + 2) % 3) * SE;
            __nv_bfloat16* sB = sA + BM * SMS;
            const int k0 = (it + 2) << 5;
#pragma unroll
            for (int r = 0; r < AUNITS; r++)
                CP16(smem_to_u32(sA + (r0 + r * 64) * SMS + kq), A2 + arow[r] + k0);
            CP16(smem_to_u32(sB + r0 * SMS + kq), B2 + brow0 + k0);
            CP16(smem_to_u32(sB + (r0 + 64) * SMS + kq), B2 + brow1 + k0);
            CP_COMMIT();
        }
        stage = (stage + 1) % 3;
    }

    // epilogue
    const bool f_silu = (flags & FLAG_SILU) != 0;
    const bool f_respre = (flags & FLAG_RESPRE) != 0;
    const bool f_comb = (flags & FLAG_COMBINE) != 0;
    const int g = lid >> 2;
    const int t2 = (lid & 3) << 1;
#pragma unroll
    for (int i = 0; i < IITER; i++) {
#pragma unroll
        for (int half = 0; half < 2; half++) {
            const int m = bm + wm * (BM / 2) + i * 16 + g + half * 8;
            int rrow = 0, ccol = 0;
            if (f_comb) { rrow = m / KEDGE; ccol = edges[E_EDGES + m]; }
#pragma unroll
            for (int j = 0; j < 4; j++) {
                const int n0 = bn + wn * 32 + j * 8 + t2;
                const long base = (long)m * Nt + n0;
                float v0 = acc[i][j][2 * half + 0];
                float v1 = acc[i][j][2 * half + 1];
                if (bias) { v0 += bias[n0]; v1 += bias[n0 + 1]; }
                if (f_comb) {
                    v0 += ArAc[(long)rrow * 256 + n0] + ArAc[(long)ccol * 256 + 128 + n0];
                    v1 += ArAc[(long)rrow * 256 + n0 + 1] + ArAc[(long)ccol * 256 + 128 + n0 + 1];
                }
                if (f_respre && res) { v0 += res[base]; v1 += res[base + 1]; }
                if (f_silu) {
                    v0 = v0 / (1.0f + __expf(-v0));
                    v1 = v1 / (1.0f + __expf(-v1));
                }
                if (!f_respre && res) { v0 += res[base]; v1 += res[base + 1]; }
                if (C) *(float2*)&C[base] = make_float2(v0, v1);
                if (sdst) {
                    __nv_bfloat16 h0 = __float2bfloat16(v0);
                    __nv_bfloat16 h1 = __float2bfloat16(v1);
                    __nv_bfloat16 l0 = __float2bfloat16(v0 - __bfloat162float(h0));
                    __nv_bfloat16 l1 = __float2bfloat16(v1 - __bfloat162float(h1));
                    __nv_bfloat16* d = sdst + (long)m * sldd + n0;
                    __nv_bfloat162 hv; hv.x = h0; hv.y = h1;
                    __nv_bfloat162 lv; lv.x = l0; lv.y = l1;
                    *(__nv_bfloat162*)&d[0] = hv;
                    *(__nv_bfloat162*)&d[Nt] = lv;
                    *(__nv_bfloat162*)&d[2 * Nt] = hv;
                }
            }
        }
    }
}

#define TCSMEM128 (3 * (128 + 128) * SMS * 2)   // 61440 B
#define TCSMEM64  (3 * (64 + 128) * SMS * 2)    // 46080 B

// ---------------- split kernel (fp32 -> [hi|lo|hi]); src row stride srcld ----------------
__global__ void splitA_kernel(const float* __restrict__ src, int srcld, int K,
                              __nv_bfloat16* __restrict__ dst, int ldd, int coff,
                              const float* __restrict__ rowscale, long total)
{
    long idx = (long)blockIdx.x * blockDim.x + threadIdx.x;
    if (idx >= total) return;
    int k = (int)(idx % K);
    long row = idx / K;
    float x = src[row * srcld + k];
    if (rowscale) x *= rowscale[row];
    wsplit1(dst + row * ldd + coff + k, K, x);
}

// ---------------- fp32 GEMM (initial MLP) ----------------
__device__ __forceinline__ unsigned long long pack2(float lo, float hi) {
    unsigned long long r;
    asm("mov.b64 %0, {%1, %2};" : "=l"(r) : "f"(lo), "f"(hi));
    return r;
}
__device__ __forceinline__ unsigned long long dup2(float v) {
    unsigned long long r;
    asm("mov.b64 %0, {%1, %1};" : "=l"(r) : "f"(v));
    return r;
}
__device__ __forceinline__ void fma2(unsigned long long& acc, unsigned long long a, unsigned long long b) {
    asm("fma.rn.f32x2 %0, %1, %2, %0;" : "+l"(acc) : "l"(a), "l"(b));
}
__device__ __forceinline__ void unpack2(unsigned long long p, float& lo, float& hi) {
    asm("mov.b64 {%0, %1}, %2;" : "=f"(lo), "=f"(hi) : "l"(p));
}

__global__ __launch_bounds__(256, 1)
void gemm128(const float* __restrict__ A, const float* __restrict__ B,
             const float* __restrict__ bias, const float* __restrict__ res,
             float* __restrict__ C, int M, int N, int K, int flags,
             long sA, long sB, long sC)
{
    A += blockIdx.z * sA; B += blockIdx.z * sB; C += blockIdx.z * sC;
    __shared__ float As[2][16][128];
    __shared__ float Bs[2][16][128];
    const int bm = blockIdx.y * 128;
    const int bn = blockIdx.x * 128;
    const int t = threadIdx.x;
    const int ty = t >> 4;
    const int tx = t & 15;

    unsigned long long acc2[8][4];
#pragma unroll
    for (int i = 0; i < 8; i++)
#pragma unroll
        for (int j = 0; j < 4; j++) acc2[i][j] = 0ull;

    const int tiles = K >> 4;
    const int a_row0 = t >> 2;
    const int a_kc = (t & 3) << 2;
    const int b_k0 = t >> 5;
    const int b_n4 = (t & 31) << 2;

    {
#pragma unroll
        for (int r = 0; r < 2; r++) {
            int row = a_row0 + r * 64;
            float4 v = *(const float4*)&A[(long)(bm + row) * K + a_kc];
            As[0][a_kc + 0][row] = v.x; As[0][a_kc + 1][row] = v.y;
            As[0][a_kc + 2][row] = v.z; As[0][a_kc + 3][row] = v.w;
        }
#pragma unroll
        for (int r = 0; r < 2; r++) {
            int k = b_k0 + r * 8;
            *(float4*)&Bs[0][k][b_n4] = *(const float4*)&B[(long)k * N + bn + b_n4];
        }
    }
    __syncthreads();

    for (int tt = 0; tt < tiles; tt++) {
        const int buf = tt & 1;
        float4 pa[2], pb[2];
        if (tt + 1 < tiles) {
            const int k0n = (tt + 1) << 4;
#pragma unroll
            for (int r = 0; r < 2; r++)
                pa[r] = *(const float4*)&A[(long)(bm + a_row0 + r * 64) * K + k0n + a_kc];
#pragma unroll
            for (int r = 0; r < 2; r++)
                pb[r] = *(const float4*)&B[(long)(k0n + b_k0 + r * 8) * N + bn + b_n4];
        }
#pragma unroll
        for (int k = 0; k < 16; k++) {
            float a[8];
            float4 a0 = *(const float4*)&As[buf][k][ty * 8];
            float4 a1 = *(const float4*)&As[buf][k][ty * 8 + 4];
            a[0] = a0.x; a[1] = a0.y; a[2] = a0.z; a[3] = a0.w;
            a[4] = a1.x; a[5] = a1.y; a[6] = a1.z; a[7] = a1.w;
            float4 b0 = *(const float4*)&Bs[buf][k][tx * 8];
            float4 b1 = *(const float4*)&Bs[buf][k][tx * 8 + 4];
            unsigned long long b2[4];
            b2[0] = pack2(b0.x, b0.y); b2[1] = pack2(b0.z, b0.w);
            b2[2] = pack2(b1.x, b1.y); b2[3] = pack2(b1.z, b1.w);
#pragma unroll
            for (int i = 0; i < 8; i++) {
                unsigned long long ad = dup2(a[i]);
#pragma unroll
                for (int j = 0; j < 4; j++) fma2(acc2[i][j], ad, b2[j]);
            }
        }
        if (tt + 1 < tiles) {
            const int nb = buf ^ 1;
#pragma unroll
            for (int r = 0; r < 2; r++) {
                int row = a_row0 + r * 64;
                As[nb][a_kc + 0][row] = pa[r].x; As[nb][a_kc + 1][row] = pa[r].y;
                As[nb][a_kc + 2][row] = pa[r].z; As[nb][a_kc + 3][row] = pa[r].w;
            }
#pragma unroll
            for (int r = 0; r < 2; r++)
                *(float4*)&Bs[nb][b_k0 + r * 8][b_n4] = pb[r];
        }
        __syncthreads();
    }

    const bool silu = (flags & FLAG_SILU) != 0;
#pragma unroll
    for (int i = 0; i < 8; i++) {
        const int m = bm + ty * 8 + i;
        float cv[8];
#pragma unroll
        for (int j = 0; j < 4; j++) unpack2(acc2[i][j], cv[2 * j], cv[2 * j + 1]);
        const long base = (long)m * N + bn + tx * 8;
#pragma unroll
        for (int j = 0; j < 8; j++) {
            float v = cv[j];
            if (bias) v += bias[bn + tx * 8 + j];
            if (silu) v = v / (1.0f + __expf(-v));
            if (res) v += res[base + j];
            cv[j] = v;
        }
        float4* cp = (float4*)&C[base];
        cp[0] = make_float4(cv[0], cv[1], cv[2], cv[3]);
        cp[1] = make_float4(cv[4], cv[5], cv[6], cv[7]);
    }
}

// ---------------- small weight-product kernel: We2 @ {Wvv, Wv, Wh1b} ----------------
__global__ void wprod_kernel(const float* __restrict__ We2, const float* __restrict__ Wv,
                             const float* __restrict__ Wvv, const float* __restrict__ Wh1,
                             float* __restrict__ MWv, float* __restrict__ W2v,
                             float* __restrict__ W2h)
{
    int l = blockIdx.z;
    int row = blockIdx.y;
    int n = threadIdx.x;
    __shared__ float a[HD];
    a[n] = We2[(long)l * HD * HD + row * HD + n];
    __syncthreads();
    const float* B;
    float* O;
    if (blockIdx.x == 0)      { B = Wvv + (long)l * HD * HD;                O = W2v; }
    else if (blockIdx.x == 1) { B = Wv + (long)l * HD * HD;                 O = MWv; }
    else                      { B = Wh1 + (long)l * 256 * HD + 128 * HD;    O = W2h; }
    float s = 0.0f;
#pragma unroll 8
    for (int k = 0; k < HD; k++) s += a[k] * B[k * HD + n];
    O[(long)l * HD * HD + row * HD + n] = s;
}

// ---------------- staging pack kernels (fp32) ----------------
__global__ void pack_We1cat_kernel(const float* __restrict__ We1, float* __restrict__ out)
{
    int idx = blockIdx.x * blockDim.x + threadIdx.x;
    if (idx >= 4 * HD * 256) return;
    int l = idx / (HD * 256);
    int rem = idx - l * HD * 256;
    int k = rem >> 8, n = rem & 255;
    const float* base = We1 + (long)l * 292 * HD;
    out[idx] = (n < HD) ? base[k * HD + n] : base[(HD + k) * HD + (n - HD)];
}
__global__ void pack_Wef_kernel(const float* __restrict__ We1, float* __restrict__ out)
{
    int idx = blockIdx.x * blockDim.x + threadIdx.x;
    if (idx >= 4 * EFK * HD) return;
    int l = idx / (EFK * HD);
    int rem = idx - l * EFK * HD;
    int k = rem >> 7, n = rem & 127;
    out[idx] = (k < EFR) ? We1[(long)l * 292 * HD + (256 + k) * HD + n] : 0.0f;
}
__global__ void pack_Wgv_kernel(const float* __restrict__ Wgv1, const float* __restrict__ Wgv2,
                                float* __restrict__ out)
{
    int idx = blockIdx.x * blockDim.x + threadIdx.x;
    if (idx >= HD * 256) return;
    int k = idx >> 8, n = idx & 255;
    out[idx] = (n < HD) ? Wgv1[k * HD + n] : Wgv2[k * HD + (n - HD)];
}
__global__ void bias_pre_kernel(const float* __restrict__ be2, const float* __restrict__ Wv,
                                const float* __restrict__ Wvv, const float* __restrict__ Wh1,
                                const float* __restrict__ bh1,
                                float* __restrict__ bWv, float* __restrict__ bWvv,
                                float* __restrict__ bh1adj)
{
    int l = blockIdx.x;
    int n = threadIdx.x;
    const float* b = be2 + l * HD;
    float s1 = 0.f, s2 = 0.f, s3 = 0.f;
    const float* w1 = Wv + (long)l * HD * HD;
    const float* w2 = Wvv + (long)l * HD * HD;
    const float* w3 = Wh1 + (long)l * 256 * HD + 128 * HD;
#pragma unroll 8
    for (int k = 0; k < HD; k++) {
        s1 += b[k] * w1[k * HD + n];
        s2 += b[k] * w2[k * HD + n];
        s3 += b[k] * w3[k * HD + n];
    }
    bWv[l * HD + n] = s1;
    bWvv[l * HD + n] = s2;
    bh1adj[l * HD + n] = bh1[l * HD + n] + 9.0f * s3;
}

// ---------------- single fused bf16 B-pack ----------------
#define NJOBS 13
struct PackJobs {
    const float* src[NJOBS];
    long sstride[NJOBS];
    long dstride[NJOBS];
    __nv_bfloat16* dst[NJOBS];
    int K[NJOBS];
    int N[NJOBS];
    int ldd[NJOBS];
    int coff[NJOBS];
    int layers[NJOBS];
    int srcN[NJOBS];   // src row width (>= N)
};
__global__ void pack_all_kernel(PackJobs J)
{
    int j = blockIdx.y;
    int l = blockIdx.z;
    if (l >= J.layers[j]) return;
    int idx = blockIdx.x * 256 + threadIdx.x;
    int KN = J.K[j] * J.N[j];
    if (idx >= KN) return;
    int k = idx / J.N[j], n = idx % J.N[j];
    float x = J.src[j][(long)l * J.sstride[j] + (long)k * J.srcN[j] + n];
    __nv_bfloat16 hi = __float2bfloat16(x);
    __nv_bfloat16 lo = __float2bfloat16(x - __bfloat162float(hi));
    __nv_bfloat16* d = J.dst[j] + (long)l * J.dstride[j] + (long)n * J.ldd[j] + J.coff[j];
    d[k] = hi;
    d[J.K[j] + k] = hi;
    d[2 * J.K[j] + k] = lo;
}

// ---------------- elementwise / reduction kernels ----------------
__global__ void edge_geom_kernel(const float* __restrict__ X, const float* __restrict__ edge_attr,
                                 const int* __restrict__ edges,
                                 float* __restrict__ unit, float* __restrict__ ef)
{
    int e = blockIdx.x * blockDim.x + threadIdx.x;
    if (e >= E_EDGES) return;
    int r = edges[e];
    int c = edges[E_EDGES + e];
    float dx = X[r * 3 + 0] - X[c * 3 + 0];
    float dy = X[r * 3 + 1] - X[c * 3 + 1];
    float dz = X[r * 3 + 2] - X[c * 3 + 2];
    float norm = sqrtf(dx * dx + dy * dy + dz * dz) + 1e-8f;
    float invn = 1.0f / norm;
    unit[e * 3 + 0] = dx * invn;
    unit[e * 3 + 1] = dy * invn;
    unit[e * 3 + 2] = dz * invn;
    const float PI_ = 3.14159265358979323846f;
    float cn = fminf(norm, 1.0f);
    float cut = 0.5f * (cosf(PI_ * cn) + 1.0f);
    float f = cut * invn;
#pragma unroll
    for (int j = 0; j < 20; j++)
        ef[(long)e * EFK + j] = sinf(norm * PI_ * (float)(j + 1)) * f;
#pragma unroll
    for (int j = 0; j < 16; j++)
        ef[(long)e * EFK + 20 + j] = edge_attr[e * 16 + j];
#pragma unroll
    for (int j = EFR; j < EFK; j++)
        ef[(long)e * EFK + j] = 0.0f;
}

__global__ void aggT_kernel(const __nv_bfloat16* __restrict__ t2, const float* __restrict__ unit,
                            __nv_bfloat16* __restrict__ aggdst, int aggld,
                            __nv_bfloat16* __restrict__ Mdst, float* __restrict__ usum)
{
    int n = blockIdx.x;
    int hh = threadIdx.x;
    float s = 0.f, mx = 0.f, my = 0.f, mz = 0.f;
#pragma unroll
    for (int j = 0; j < KEDGE; j++) {
        long e = (long)n * KEDGE + j;
        float tt = __bfloat162float(t2[e * 384 + hh]) + __bfloat162float(t2[e * 384 + 128 + hh]);
        float ux = unit[e * 3 + 0];
        float uy = unit[e * 3 + 1];
        float uz = unit[e * 3 + 2];
        s += tt; mx += tt * ux; my += tt * uy; mz += tt * uz;
    }
    wsplit1(aggdst + (long)n * aggld + hh, 128, s);
    wsplit1(Mdst + (long)(3 * n + 0) * 384 + hh, 128, mx);
    wsplit1(Mdst + (long)(3 * n + 1) * 384 + hh, 128, my);
    wsplit1(Mdst + (long)(3 * n + 2) * 384 + hh, 128, mz);
    if (hh < 3) {
        float u = 0.f;
#pragma unroll
        for (int j = 0; j < KEDGE; j++) u += unit[((long)n * KEDGE + j) * 3 + hh];
        usum[n * 3 + hh] = u;
    }
}

__global__ void vupdate_kernel(const float* __restrict__ vin, float* __restrict__ vout,
                               const float* __restrict__ mvv, const float* __restrict__ vagg,
                               const float* __restrict__ usum, const float* __restrict__ bWv,
                               const int* __restrict__ edges)
{
    int n = blockIdx.x;
    int hh = threadIdx.x;
    float bw = bWv[hh];
    float a0 = vagg[(long)n * 384 + hh]       + usum[n * 3 + 0] * bw;
    float a1 = vagg[(long)n * 384 + 128 + hh] + usum[n * 3 + 1] * bw;
    float a2 = vagg[(long)n * 384 + 256 + hh] + usum[n * 3 + 2] * bw;
    if (vin) {
        a0 += vin[(long)n * 384 + hh];
        a1 += vin[(long)n * 384 + 128 + hh];
        a2 += vin[(long)n * 384 + 256 + hh];
#pragma unroll
        for (int j = 0; j < KEDGE; j++) {
            long e = (long)n * KEDGE + j;
            int c = edges[E_EDGES + e];
            float b = mvv[e * HD + hh];
            a0 += b * vin[(long)c * 384 + hh];
            a1 += b * vin[(long)c * 384 + 128 + hh];
            a2 += b * vin[(long)c * 384 + 256 + hh];
        }
    }
    vout[(long)n * 384 + hh] = a0;
    vout[(long)n * 384 + 128 + hh] = a1;
    vout[(long)n * 384 + 256 + hh] = a2;
}

__global__ void meanh1_kernel(const float* __restrict__ hintra, float* __restrict__ part)
{
    int s = blockIdx.x;
    int c = blockIdx.y;
    int k = threadIdx.x;
    float acc = 0.0f;
    const float* p = hintra + ((long)s * SEGSZ + c * 64) * HD + k;
#pragma unroll 8
    for (int u = 0; u < 64; u++) acc += p[u * HD];
    part[(s * 8 + c) * HD + k] = acc;
}

// attn: reads 8-way partials of opposite segment directly (meanh2 fused)
__global__ void attn_kernel(const float* __restrict__ hintra, const float* __restrict__ part,
                            float* __restrict__ w)
{
    int s = blockIdx.x;
    int t = threadIdx.x;
    __shared__ float sm[HD];
    __shared__ float red[SEGSZ];
    int opp = s ^ 1;
    if (t < HD) {
        float a = 0.0f;
#pragma unroll
        for (int c = 0; c < 8; c++) a += part[(opp * 8 + c) * HD + t];
        sm[t] = a * (1.0f / (float)SEGSZ);
    }
    __syncthreads();
    int node = s * SEGSZ + t;
    const float* hr = hintra + (long)node * HD;
    float sc = 0.0f;
#pragma unroll 8
    for (int k = 0; k < HD; k++) sc += hr[k] * sm[k];
    red[t] = sc;
    __syncthreads();
    for (int st = SEGSZ / 2; st > 0; st >>= 1) {
        if (t < st) red[t] = fmaxf(red[t], red[t + st]);
        __syncthreads();
    }
    float mx = red[0];
    __syncthreads();
    float ex = expf(sc - mx);
    red[t] = ex;
    __syncthreads();
    for (int st = SEGSZ / 2; st > 0; st >>= 1) {
        if (t < st) red[t] += red[t + st];
        __syncthreads();
    }
    w[node] = ex / red[0];
}

__global__ void v2n_kernel(const float* __restrict__ vp, float* __restrict__ v2n)
{
    int idx = blockIdx.x * blockDim.x + threadIdx.x;
    if (idx >= N_NODES * HD) return;
    int n = idx / HD;
    int k = idx % HD;
    float a = vp[(long)(n * 3 + 0) * 256 + HD + k];
    float b = vp[(long)(n * 3 + 1) * 256 + HD + k];
    float c = vp[(long)(n * 3 + 2) * 256 + HD + k];
    v2n[idx] = sqrtf(a * a + b * b + c * c + 1e-8f);
}

__global__ void pv_kernel(const float* __restrict__ vp, const float* __restrict__ mix,
                          const float* __restrict__ Wf, float* __restrict__ pv)
{
    int n = blockIdx.x;
    int k = threadIdx.x;
    __shared__ float sd[3][HD];
    float hf = mix[(long)n * 256 + k];
    float bg = mix[(long)n * 256 + HD + k];
    float s = hf * bg;
    sd[0][k] = vp[(long)(n * 3 + 0) * 256 + k] * s;
    sd[1][k] = vp[(long)(n * 3 + 1) * 256 + k] * s;
    sd[2][k] = vp[(long)(n * 3 + 2) * 256 + k] * s;
    __syncthreads();
    if (k < 27) {
        int o = k / 3, c = k % 3;
        float acc = 0.0f;
#pragma unroll 8
        for (int kk = 0; kk < HD; kk++) acc += sd[c][kk] * Wf[kk * 9 + o];
        pv[(long)n * 27 + k] = acc;
    }
}

__global__ void predsum_kernel(const float* __restrict__ pv, float* __restrict__ pred)
{
    int s = blockIdx.x;
    int j = threadIdx.x;
    if (j >= 27) return;
    float acc = 0.0f;
    for (int u = 0; u < SEGSZ; u++)
        acc += pv[(long)(s * SEGSZ + u) * 27 + j];
    pred[s * 27 + j] = acc;
}

__global__ void final_kernel(const float* __restrict__ pred, float* __restrict__ out)
{
    int s = threadIdx.x;
    if (s >= NSEG) return;
    const float* p = pred + s * 27;
#pragma unroll
    for (int r = 0; r < 3; r++) {
#pragma unroll
        for (int c = 0; c < 3; c++) {
            float A = p[0 * 3 + r] * p[1 * 3 + c]
                    + p[3 * 3 + r] * p[2 * 3 + c]
                    + p[4 * 3 + r] * p[5 * 3 + c]
                    + p[7 * 3 + r] * p[6 * 3 + c];
            out[s * 12 + r * 4 + c] = A * 100.0f;
        }
        out[s * 12 + r * 4 + 3] = p[8 * 3 + r] * 10.0f;
    }
}

// ---------------- host driver ----------------
static void launch_tc(const __nv_bfloat16* A2, int lda, int Ktot, const __nv_bfloat16* B2,
                      const float* bias, const float* res, float* C, int M, int Nt, int flags,
                      __nv_bfloat16* sdst = nullptr, int sldd = 0,
                      const int* edges = nullptr, const float* ArAc = nullptr,
                      int bmtile = 128, cudaStream_t st = 0)
{
    if (bmtile == 64) {
        dim3 grid(Nt / 128, M / 64);
        tcgemm<64><<<grid, 256, TCSMEM64, st>>>(A2, lda, Ktot, B2, bias, res, C, Nt, flags,
                                                sdst, sldd, edges, ArAc);
    } else {
        dim3 grid(Nt / 128, M / 128);
        tcgemm<128><<<grid, 256, TCSMEM128, st>>>(A2, lda, Ktot, B2, bias, res, C, Nt, flags,
                                                  sdst, sldd, edges, ArAc);
    }
}

static void launch_gemm(const float* A, const float* B, const float* bias,
                        const float* res, float* C, int M, int N, int K, int flags,
                        int batch = 1, long sA = 0, long sB = 0, long sC = 0)
{
    dim3 grid(N / 128, M / 128, batch);
    gemm128<<<grid, 256>>>(A, B, bias, res, C, M, N, K, flags, sA, sB, sC);
}

static void launch_split(const float* src, int srcld, int M, int K,
                         __nv_bfloat16* dst, int ldd, int coff, const float* rowscale)
{
    long total = (long)M * K;
    splitA_kernel<<<(int)((total + 255) / 256), 256>>>(src, srcld, K, dst, ldd, coff,
                                                       rowscale, total);
}

template <typename T>
static T* sym(const void* s)
{
    void* p = nullptr;
    cudaGetSymbolAddress(&p, s);
    return (T*)p;
}

extern "C" void kernel_launch(void* const* d_in, const int* in_sizes, int n_in,
                              void* d_out, int out_size)
{
    const float* X        = (const float*)d_in[0];
    const float* node_attr= (const float*)d_in[1];
    const float* edge_attr= (const float*)d_in[2];
    const float* W_in1    = (const float*)d_in[3];
    const float* b_in1    = (const float*)d_in[4];
    const float* W_in2    = (const float*)d_in[5];
    const float* b_in2    = (const float*)d_in[6];
    const float* We1      = (const float*)d_in[7];
    const float* be1      = (const float*)d_in[8];
    const float* We2      = (const float*)d_in[9];
    const float* be2      = (const float*)d_in[10];
    const float* Wv       = (const float*)d_in[11];
    const float* Wvv      = (const float*)d_in[12];
    const float* Wh1      = (const float*)d_in[13];
    const float* bh1      = (const float*)d_in[14];
    const float* Wh2      = (const float*)d_in[15];
    const float* bh2      = (const float*)d_in[16];
    const float* Wi1      = (const float*)d_in[17];
    const float* bi1      = (const float*)d_in[18];
    const float* Wi2      = (const float*)d_in[19];
    const float* bi2      = (const float*)d_in[20];
    const float* Wgv1     = (const float*)d_in[21];
    const float* Wgv2     = (const float*)d_in[22];
    const float* Wg1      = (const float*)d_in[23];
    const float* bg1      = (const float*)d_in[24];
    const float* Wg2      = (const float*)d_in[25];
    const float* bg2      = (const float*)d_in[26];
    const float* Wf       = (const float*)d_in[27];
    const int*   edges    = (const int*)d_in[28];
    float* out = (float*)d_out;

    static bool attr_done = false;
    static cudaStream_t s2;
    static cudaEvent_t evT, evAgg, evV;
    if (!attr_done) {
        cudaFuncSetAttribute(tcgemm<128>, cudaFuncAttributeMaxDynamicSharedMemorySize, TCSMEM128);
        cudaFuncSetAttribute(tcgemm<64>, cudaFuncAttributeMaxDynamicSharedMemorySize, TCSMEM64);
        cudaStreamCreateWithFlags(&s2, cudaStreamNonBlocking);
        cudaEventCreateWithFlags(&evT, cudaEventDisableTiming);
        cudaEventCreateWithFlags(&evAgg, cudaEventDisableTiming);
        cudaEventCreateWithFlags(&evV, cudaEventDisableTiming);
        attr_done = true;
    }

    float* p_t0     = sym<float>(g_t0);
    float* p_h      = sym<float>(g_h);
    float* p_ArAc   = sym<float>(g_ArAc);
    float* p_hintra = sym<float>(g_hintra);
    float* p_v2n    = sym<float>(g_v2n);
    float* p_mix    = sym<float>(g_mix);
    float* p_ef     = sym<float>(g_ef);
    float* p_mvv    = sym<float>(g_mvv);
    float* p_unit   = sym<float>(g_unit);
    float* p_usum   = sym<float>(g_usum);
    float* p_va     = sym<float>(g_va);
    float* p_vb     = sym<float>(g_vb);
    float* p_vagg   = sym<float>(g_vagg);
    float* p_vp     = sym<float>(g_vp);
    float* p_w      = sym<float>(g_w);
    float* p_meanp  = sym<float>(g_meanp);
    float* p_pv     = sym<float>(g_pv);
    float* p_pred   = sym<float>(g_pred);
    float* p_We1cat = sym<float>(g_We1cat);
    float* p_Wef    = sym<float>(g_Wef);
    float* p_W2v    = sym<float>(g_W2v);
    float* p_MWv    = sym<float>(g_MWv);
    float* p_W2h    = sym<float>(g_W2h);
    float* p_Wgvcat = sym<float>(g_Wgvcat);
    float* p_bWv    = sym<float>(g_bWv);
    float* p_bWvv   = sym<float>(g_bWvv);
    float* p_bh1adj = sym<float>(g_bh1adj);

    __nv_bfloat16* pa_cat = sym<__nv_bfloat16>(a2_cat);
    __nv_bfloat16* pa_u   = sym<__nv_bfloat16>(a2_u);
    __nv_bfloat16* pa_x   = sym<__nv_bfloat16>(a2_x);
    __nv_bfloat16* pa_t   = sym<__nv_bfloat16>(a2_t);
    __nv_bfloat16* pa_ef  = sym<__nv_bfloat16>(a2_ef);
    __nv_bfloat16* pa_M   = sym<__nv_bfloat16>(a2_M);
    __nv_bfloat16* pb_We1 = sym<__nv_bfloat16>(b2_We1cat);
    __nv_bfloat16* pb_Wef = sym<__nv_bfloat16>(b2_Wef);
    __nv_bfloat16* pb_W2v = sym<__nv_bfloat16>(b2_W2v);
    __nv_bfloat16* pb_MWv = sym<__nv_bfloat16>(b2_MWv);
    __nv_bfloat16* pb_Wh1 = sym<__nv_bfloat16>(b2_Wh1);
    __nv_bfloat16* pb_Wh2 = sym<__nv_bfloat16>(b2_Wh2);
    __nv_bfloat16* pb_Wi1 = sym<__nv_bfloat16>(b2_Wi1);
    __nv_bfloat16* pb_Wi2 = sym<__nv_bfloat16>(b2_Wi2);
    __nv_bfloat16* pb_Wgv = sym<__nv_bfloat16>(b2_Wgv);
    __nv_bfloat16* pb_Wg1 = sym<__nv_bfloat16>(b2_Wg1);
    __nv_bfloat16* pb_Wg2 = sym<__nv_bfloat16>(b2_Wg2);

    // ---- weight staging ----
    pack_We1cat_kernel<<<(4 * HD * 256 + 255) / 256, 256>>>(We1, p_We1cat);
    pack_Wef_kernel<<<(4 * EFK * HD + 255) / 256, 256>>>(We1, p_Wef);
    pack_Wgv_kernel<<<(HD * 256 + 255) / 256, 256>>>(Wgv1, Wgv2, p_Wgvcat);
    {
        dim3 g(3, HD, 4);
        wprod_kernel<<<g, HD>>>(We2, Wv, Wvv, Wh1, p_MWv, p_W2v, p_W2h);
    }
    bias_pre_kernel<<<4, HD>>>(be2, Wv, Wvv, Wh1, bh1, p_bWv, p_bWvv, p_bh1adj);

    // ---- single fused bf16 B-pack ----
    {
        PackJobs J;
        auto set = [&](int j, const float* src, long ss, int K, int N,
                       __nv_bfloat16* dst, long ds, int ldd, int coff, int layers,
                       int srcN) {
            J.src[j] = src; J.sstride[j] = ss; J.K[j] = K; J.N[j] = N;
            J.dst[j] = dst; J.dstride[j] = ds; J.ldd[j] = ldd; J.coff[j] = coff;
            J.layers[j] = layers; J.srcN[j] = srcN;
        };
        set(0,  p_We1cat, (long)HD * 256, 128, 256, pb_We1, (long)256 * 384, 384, 0, 4, 256);
        set(1,  p_Wef, (long)EFK * HD, EFR, 128, pb_Wef, (long)128 * 128, 128, 0, 4, 128);
        set(2,  p_W2v, (long)HD * HD, 128, 128, pb_W2v, (long)128 * 384, 384, 0, 4, 128);
        set(3,  p_MWv, (long)HD * HD, 128, 128, pb_MWv, (long)128 * 384, 384, 0, 4, 128);
        set(4,  p_W2h, (long)HD * HD, 128, 128, pb_Wh1, (long)128 * 768, 768, 384, 4, 128);
        set(5,  Wh1, (long)256 * HD, 128, 128, pb_Wh1, (long)128 * 768, 768, 0, 4, 128);
        set(6,  Wh2, (long)HD * HD, 128, 128, pb_Wh2, (long)128 * 384, 384, 0, 4, 128);
        set(7,  Wi1, (long)HD * HD, 128, 128, pb_Wi1, (long)128 * 384, 384, 0, 4, 128);
        set(8,  Wi2, (long)HD * HD, 128, 128, pb_Wi2, (long)128 * 384, 384, 0, 4, 128);
        set(9,  p_Wgvcat, 0, 128, 256, pb_Wgv, 0, 384, 0, 1, 256);
        set(10, Wg1, 0, 128, 128, pb_Wg1, 0, 768, 0, 1, 128);
        set(11, Wg1 + 128 * HD, 0, 128, 128, pb_Wg1, 0, 768, 384, 1, 128);
        set(12, Wg2, 0, 128, 256, pb_Wg2, 0, 384, 0, 1, 256);
        dim3 grid(128, NJOBS, 4);
        pack_all_kernel<<<grid, 256>>>(J);
    }

    // edge geometry + split ef (real K=36 -> [hi36|lo36|hi36|pad] = 128)
    edge_geom_kernel<<<(E_EDGES + 255) / 256, 256>>>(X, edge_attr, edges, p_unit, p_ef);
    launch_split(p_ef, EFK, E_EDGES, EFR, pa_ef, 128, 0, nullptr);

    // h = silu(node_attr @ W_in1 + b_in1) @ W_in2 + b_in2  (fp32), split into pa_cat[0:384]
    launch_gemm(node_attr, W_in1, b_in1, nullptr, p_t0, N_NODES, HD, 64, FLAG_SILU);
    launch_gemm(p_t0, W_in2, b_in2, nullptr, p_h, N_NODES, HD, HD, 0);
    launch_split(p_h, HD, N_NODES, HD, pa_cat, 768, 0, nullptr);

    float* vin = nullptr;
    float* vbuf0 = p_va;
    float* vbuf1 = p_vb;

    for (int i = 0; i < 4; i++) {
        const float* be1_i = be1 + i * HD;
        const float* bh2_i = bh2 + i * HD;
        const float* bi1_i = bi1 + i * HD;
        const float* bi2_i = bi2 + i * HD;
        float* vout = (i & 1) ? vbuf1 : vbuf0;

        // [Ar|Ac] = h @ [W_r|W_c]
        launch_tc(pa_cat, 768, 384, pb_We1 + (long)i * 256 * 384,
                  nullptr, nullptr, p_ArAc, N_NODES, 256, 0);

        // protect pa_t / pa_M / p_usum: previous layer's v-chain must be done
        if (i > 0) cudaStreamWaitEvent(0, evV, 0);

        // t = silu(ef@Wef + be1 + Ar[row] + Ac[col]) -> split pa_t   (K=128 now)
        launch_tc(pa_ef, 128, 128, pb_Wef + (long)i * 128 * 128,
                  be1_i, nullptr, nullptr, E_EDGES, 128, FLAG_SILU | FLAG_COMBINE,
                  pa_t, 384, edges, p_ArAc);
        cudaEventRecord(evT, 0);

        // ---- v-chain forked to s2 ----
        cudaStreamWaitEvent(s2, evT, 0);
        if (i > 0)
            launch_tc(pa_t, 384, 384, pb_W2v + (long)i * 128 * 384,
                      p_bWvv + i * HD, nullptr, p_mvv, E_EDGES, 128, 0,
                      nullptr, 0, nullptr, nullptr, 128, s2);

        // aggregate t (main)
        aggT_kernel<<<N_NODES, HD>>>(pa_t, p_unit, pa_cat + 384, 768, pa_M, p_usum);
        cudaEventRecord(evAgg, 0);

        // s2: vagg = Mt @ (We2@Wv), then vupdate
        cudaStreamWaitEvent(s2, evAgg, 0);
        launch_tc(pa_M, 384, 384, pb_MWv + (long)i * 128 * 384,
                  nullptr, nullptr, p_vagg, 3 * N_NODES, 128, 0,
                  nullptr, 0, nullptr, nullptr, 128, s2);
        vupdate_kernel<<<N_NODES, HD, 0, s2>>>(vin, vout, p_mvv, p_vagg, p_usum,
                                               p_bWv + i * HD, edges);
        cudaEventRecord(evV, s2);

        // ---- h-chain on main ----
        launch_tc(pa_cat, 768, 768, pb_Wh1 + (long)i * 128 * 768,
                  p_bh1adj + i * HD, nullptr, nullptr, N_NODES, 128, FLAG_SILU, pa_u, 384,
                  nullptr, nullptr, 64);
        launch_tc(pa_u, 384, 384, pb_Wh2 + (long)i * 128 * 384,
                  bh2_i, p_h, p_hintra, N_NODES, 128, 0, nullptr, 0,
                  nullptr, nullptr, 64);

        // segment attention (meanh2 fused into attn)
        {
            dim3 g1(NSEG, 8);
            meanh1_kernel<<<g1, HD>>>(p_hintra, p_meanp);
        }
        attn_kernel<<<NSEG, SEGSZ>>>(p_hintra, p_meanp, p_w);
        launch_split(p_hintra, HD, N_NODES, HD, pa_x, 384, 0, p_w);
        launch_tc(pa_x, 384, 384, pb_Wi1 + (long)i * 128 * 384,
                  bi1_i, nullptr, nullptr, N_NODES, 128, FLAG_SILU, pa_u, 384,
                  nullptr, nullptr, 64);
        launch_tc(pa_u, 384, 384, pb_Wi2 + (long)i * 128 * 384,
                  bi2_i, p_hintra, p_h, N_NODES, 128, 0, pa_cat, 768,
                  nullptr, nullptr, 64);

        vin = vout;
    }

    // join v-chain before final v projection
    cudaStreamWaitEvent(0, evV, 0);

    // [v1 | v2] = v @ [Wgv1 | Wgv2]
    launch_split(vin, HD, 3 * N_NODES, HD, pa_M, 384, 0, nullptr);
    launch_tc(pa_M, 384, 384, pb_Wgv, nullptr, nullptr, p_vp, 3 * N_NODES, 256, 0);
    v2n_kernel<<<(N_NODES * HD + 255) / 256, 256>>>(p_vp, p_v2n);

    // mix = silu([h|v2n] @ Wg1 + bg1) @ Wg2 + bg2
    launch_split(p_v2n, HD, N_NODES, HD, pa_cat, 768, 384, nullptr);
    launch_tc(pa_cat, 768, 768, pb_Wg1, bg1, nullptr, nullptr, N_NODES, 128, FLAG_SILU,
              pa_u, 384, nullptr, nullptr, 64);
    launch_tc(pa_u, 384, 384, pb_Wg2, bg2, nullptr, p_mix, N_NODES, 256, 0,
              nullptr, 0, nullptr, nullptr, 64);

    // epilogue
    pv_kernel<<<N_NODES, HD>>>(p_vp, p_mix, Wf, p_pv);
    predsum_kernel<<<NSEG, 32>>>(p_pv, p_pred);
    final_kernel<<<1, 32>>>(p_pred, out);
}

// round 16
// speedup vs baseline: 1.0535x; 1.0208x over previous
#include <cuda_runtime.h>
#include <cuda_bf16.h>
#include <math.h>
#include <stdint.h>

#define N_NODES 16384
#define E_EDGES 147456
#define HD 128
#define NSEG 32
#define SEGSZ 512
#define KEDGE 9
#define EFK 64
#define EFR 36   // real ef feature count

#define FLAG_SILU 1
#define FLAG_RESPRE 2
#define FLAG_COMBINE 4

// ---------------- fp32 scratch ----------------
__device__ float g_t0[N_NODES * HD];
__device__ float g_h[N_NODES * HD];
__device__ float g_ArAc[N_NODES * 2 * HD];
__device__ float g_hintra[N_NODES * HD];
__device__ float g_v2n[N_NODES * HD];
__device__ float g_mix[N_NODES * 2 * HD];
__device__ float g_ef[(long)E_EDGES * EFK];
__device__ float g_mvv[(long)E_EDGES * HD];
__device__ float g_unit[E_EDGES * 3];
__device__ float g_usum[N_NODES * 3];
__device__ float g_va[N_NODES * 3 * HD];
__device__ float g_vb[N_NODES * 3 * HD];
__device__ float g_vagg[N_NODES * 3 * HD];
__device__ float g_vp[(long)N_NODES * 3 * 256];
__device__ float g_w[N_NODES];
__device__ float g_meanp[NSEG * 8 * HD];
__device__ float g_pv[N_NODES * 27];
__device__ float g_pred[NSEG * 27];
// fp32 weight staging
__device__ float g_We1cat[4 * HD * 256];
__device__ float g_Wef[4 * EFK * HD];
__device__ float g_W2v[4 * HD * HD];   // We2 @ Wvv
__device__ float g_MWv[4 * HD * HD];   // We2 @ Wv
__device__ float g_W2h[4 * HD * HD];   // We2 @ Wh1b
__device__ float g_Wgvcat[HD * 256];
__device__ float g_bWv[4 * HD];
__device__ float g_bWvv[4 * HD];
__device__ float g_bh1adj[4 * HD];     // bh1 + 9*be2 @ Wh1b

// ---------------- bf16 split operand buffers (zero-initialized device globals) ----------------
__device__ __align__(16) __nv_bfloat16 a2_cat[(long)N_NODES * 768];
__device__ __align__(16) __nv_bfloat16 a2_u[(long)N_NODES * 384];
__device__ __align__(16) __nv_bfloat16 a2_x[(long)N_NODES * 384];
__device__ __align__(16) __nv_bfloat16 a2_t[(long)E_EDGES * 384];
__device__ __align__(16) __nv_bfloat16 a2_ef[(long)E_EDGES * 128];   // [hi36|lo36|hi36|pad]
__device__ __align__(16) __nv_bfloat16 a2_M[(long)3 * N_NODES * 384];
__device__ __align__(16) __nv_bfloat16 b2_We1cat[4 * 256 * 384];
__device__ __align__(16) __nv_bfloat16 b2_Wef[4 * 128 * 128];        // [hi36|hi36|lo36|pad]
__device__ __align__(16) __nv_bfloat16 b2_W2v[4 * 128 * 384];
__device__ __align__(16) __nv_bfloat16 b2_MWv[4 * 128 * 384];
__device__ __align__(16) __nv_bfloat16 b2_Wh1[4 * 128 * 768];
__device__ __align__(16) __nv_bfloat16 b2_Wh2[4 * 128 * 384];
__device__ __align__(16) __nv_bfloat16 b2_Wi1[4 * 128 * 384];
__device__ __align__(16) __nv_bfloat16 b2_Wi2[4 * 128 * 384];
__device__ __align__(16) __nv_bfloat16 b2_Wgv[256 * 384];
__device__ __align__(16) __nv_bfloat16 b2_Wg1[128 * 768];
__device__ __align__(16) __nv_bfloat16 b2_Wg2[256 * 384];

// ---------------- helpers ----------------
__device__ __forceinline__ uint32_t smem_to_u32(const void* p) {
    uint32_t a;
    asm("{ .reg .u64 t; cvta.to.shared.u64 t, %1; cvt.u32.u64 %0, t; }" : "=r"(a) : "l"(p));
    return a;
}
__device__ __forceinline__ void wsplit1(__nv_bfloat16* d, int K, float x) {
    __nv_bfloat16 hi = __float2bfloat16(x);
    __nv_bfloat16 lo = __float2bfloat16(x - __bfloat162float(hi));
    d[0] = hi; d[K] = lo; d[2 * K] = hi;
}
#define CP16(dst, src) \
    asm volatile("cp.async.cg.shared.global [%0], [%1], 16;" :: "r"(dst), "l"(src) : "memory")
#define CP_COMMIT() asm volatile("cp.async.commit_group;" ::: "memory")
#define CP_WAIT1()  asm volatile("cp.async.wait_group 1;" ::: "memory")
#define CP_WAIT0()  asm volatile("cp.async.wait_group 0;" ::: "memory")

// ---------------- bf16-split tensor-core GEMM: mma.sync + 3-stage cp.async ----------------
#define SMS 40

template <int BM>
__global__ __launch_bounds__(256, 2)
void tcgemm(const __nv_bfloat16* __restrict__ A2, int lda, int Ktot,
            const __nv_bfloat16* __restrict__ B2,
            const float* __restrict__ bias, const float* __restrict__ res,
            float* __restrict__ C, int Nt, int flags,
            __nv_bfloat16* __restrict__ sdst, int sldd,
            const int* __restrict__ edges, const float* __restrict__ ArAc)
{
    constexpr int AUNITS = BM / 64;
    constexpr int IITER = BM / 32;
    constexpr int SE = (BM + 128) * SMS;

    extern __shared__ __align__(16) char smraw[];
    __nv_bfloat16* sm = (__nv_bfloat16*)smraw;

    const int t = threadIdx.x;
    const int lid = t & 31;
    const int wid = t >> 5;
    const int wm = wid & 1;
    const int wn = wid >> 1;
    const int bm = blockIdx.y * BM;
    const int bn = blockIdx.x * 128;

    float acc[IITER][4][4];
#pragma unroll
    for (int i = 0; i < IITER; i++)
#pragma unroll
        for (int j = 0; j < 4; j++)
#pragma unroll
            for (int r = 0; r < 4; r++) acc[i][j][r] = 0.0f;

    const int r0 = t >> 2;
    const int kq = (t & 3) << 3;

    const int a_row = wm * (BM / 2) + (lid & 7) + ((lid >> 3) & 1) * 8;
    const int a_col = ((lid >> 4) & 1) * 8;
    const int a_off = a_row * SMS + a_col;
    const int b_row = wn * 32 + (lid & 7);
    const int b_col = ((lid >> 3) & 1) * 8;
    const int b_off = b_row * SMS + b_col;

    const int iters = Ktot >> 5;

    long arow[AUNITS];
#pragma unroll
    for (int r = 0; r < AUNITS; r++) arow[r] = (long)(bm + r0 + r * 64) * lda + kq;
    const long brow0 = (long)(bn + r0) * Ktot + kq;
    const long brow1 = (long)(bn + r0 + 64) * Ktot + kq;

#pragma unroll
    for (int p = 0; p < 2; p++) {
        __nv_bfloat16* sA = sm + p * SE;
        __nv_bfloat16* sB = sA + BM * SMS;
        const int k0 = p << 5;
#pragma unroll
        for (int r = 0; r < AUNITS; r++)
            CP16(smem_to_u32(sA + (r0 + r * 64) * SMS + kq), A2 + arow[r] + k0);
        CP16(smem_to_u32(sB + r0 * SMS + kq), B2 + brow0 + k0);
        CP16(smem_to_u32(sB + (r0 + 64) * SMS + kq), B2 + brow1 + k0);
        CP_COMMIT();
    }

    int stage = 0;
    for (int it = 0; it < iters; it++) {
        if (it + 1 < iters) { CP_WAIT1(); } else { CP_WAIT0(); }
        __syncthreads();

        const uint32_t aBase = smem_to_u32(sm + stage * SE);
        const uint32_t bBase = aBase + BM * SMS * 2;
#pragma unroll
        for (int ks = 0; ks < 2; ks++) {
            uint32_t a[IITER][4];
#pragma unroll
            for (int i = 0; i < IITER; i++) {
                const uint32_t addr = aBase + 2u * (a_off + i * 16 * SMS + ks * 16);
                asm volatile(
                    "ldmatrix.sync.aligned.m8n8.x4.shared.b16 {%0,%1,%2,%3}, [%4];"
                    : "=r"(a[i][0]), "=r"(a[i][1]), "=r"(a[i][2]), "=r"(a[i][3])
                    : "r"(addr));
            }
            uint32_t b[4][2];
#pragma unroll
            for (int j = 0; j < 4; j++) {
                const uint32_t addr = bBase + 2u * (b_off + j * 8 * SMS + ks * 16);
                asm volatile(
                    "ldmatrix.sync.aligned.m8n8.x2.shared.b16 {%0,%1}, [%2];"
                    : "=r"(b[j][0]), "=r"(b[j][1])
                    : "r"(addr));
            }
#pragma unroll
            for (int i = 0; i < IITER; i++)
#pragma unroll
                for (int j = 0; j < 4; j++) {
                    asm volatile(
                        "mma.sync.aligned.m16n8k16.row.col.f32.bf16.bf16.f32 "
                        "{%0,%1,%2,%3}, {%4,%5,%6,%7}, {%8,%9}, {%0,%1,%2,%3};"
                        : "+f"(acc[i][j][0]), "+f"(acc[i][j][1]),
                          "+f"(acc[i][j][2]), "+f"(acc[i][j][3])
                        : "r"(a[i][0]), "r"(a[i][1]), "r"(a[i][2]), "r"(a[i][3]),
                          "r"(b[j][0]), "r"(b[j][1]));
                }
        }

        if (it + 2 < iters) {
            __nv_bfloat16* sA = sm + ((stage + 2) % 3) * SE;
            __nv_bfloat16* sB = sA + BM * SMS;
            const int k0 = (it + 2) << 5;
#pragma unroll
            for (int r = 0; r < AUNITS; r++)
                CP16(smem_to_u32(sA + (r0 + r * 64) * SMS + kq), A2 + arow[r] + k0);
            CP16(smem_to_u32(sB + r0 * SMS + kq), B2 + brow0 + k0);
            CP16(smem_to_u32(sB + (r0 + 64) * SMS + kq), B2 + brow1 + k0);
            CP_COMMIT();
        }
        stage = (stage + 1) % 3;
    }

    // epilogue
    const bool f_silu = (flags & FLAG_SILU) != 0;
    const bool f_respre = (flags & FLAG_RESPRE) != 0;
    const bool f_comb = (flags & FLAG_COMBINE) != 0;
    const int g = lid >> 2;
    const int t2 = (lid & 3) << 1;
#pragma unroll
    for (int i = 0; i < IITER; i++) {
#pragma unroll
        for (int half = 0; half < 2; half++) {
            const int m = bm + wm * (BM / 2) + i * 16 + g + half * 8;
            int rrow = 0, ccol = 0;
            if (f_comb) { rrow = m / KEDGE; ccol = edges[E_EDGES + m]; }
#pragma unroll
            for (int j = 0; j < 4; j++) {
                const int n0 = bn + wn * 32 + j * 8 + t2;
                const long base = (long)m * Nt + n0;
                float v0 = acc[i][j][2 * half + 0];
                float v1 = acc[i][j][2 * half + 1];
                if (bias) { v0 += bias[n0]; v1 += bias[n0 + 1]; }
                if (f_comb) {
                    v0 += ArAc[(long)rrow * 256 + n0] + ArAc[(long)ccol * 256 + 128 + n0];
                    v1 += ArAc[(long)rrow * 256 + n0 + 1] + ArAc[(long)ccol * 256 + 128 + n0 + 1];
                }
                if (f_respre && res) { v0 += res[base]; v1 += res[base + 1]; }
                if (f_silu) {
                    v0 = v0 / (1.0f + __expf(-v0));
                    v1 = v1 / (1.0f + __expf(-v1));
                }
                if (!f_respre && res) { v0 += res[base]; v1 += res[base + 1]; }
                if (C) *(float2*)&C[base] = make_float2(v0, v1);
                if (sdst) {
                    __nv_bfloat16 h0 = __float2bfloat16(v0);
                    __nv_bfloat16 h1 = __float2bfloat16(v1);
                    __nv_bfloat16 l0 = __float2bfloat16(v0 - __bfloat162float(h0));
                    __nv_bfloat16 l1 = __float2bfloat16(v1 - __bfloat162float(h1));
                    __nv_bfloat16* d = sdst + (long)m * sldd + n0;
                    __nv_bfloat162 hv; hv.x = h0; hv.y = h1;
                    __nv_bfloat162 lv; lv.x = l0; lv.y = l1;
                    *(__nv_bfloat162*)&d[0] = hv;
                    *(__nv_bfloat162*)&d[Nt] = lv;
                    *(__nv_bfloat162*)&d[2 * Nt] = hv;
                }
            }
        }
    }
}

#define TCSMEM128 (3 * (128 + 128) * SMS * 2)   // 61440 B
#define TCSMEM64  (3 * (64 + 128) * SMS * 2)    // 46080 B

// ---------------- split kernel (fp32 -> [hi|lo|hi]); src row stride srcld ----------------
__global__ void splitA_kernel(const float* __restrict__ src, int srcld, int K,
                              __nv_bfloat16* __restrict__ dst, int ldd, int coff,
                              const float* __restrict__ rowscale, long total)
{
    long idx = (long)blockIdx.x * blockDim.x + threadIdx.x;
    if (idx >= total) return;
    int k = (int)(idx % K);
    long row = idx / K;
    float x = src[row * srcld + k];
    if (rowscale) x *= rowscale[row];
    wsplit1(dst + row * ldd + coff + k, K, x);
}

// ---------------- fp32 GEMM (initial MLP) ----------------
__device__ __forceinline__ unsigned long long pack2(float lo, float hi) {
    unsigned long long r;
    asm("mov.b64 %0, {%1, %2};" : "=l"(r) : "f"(lo), "f"(hi));
    return r;
}
__device__ __forceinline__ unsigned long long dup2(float v) {
    unsigned long long r;
    asm("mov.b64 %0, {%1, %1};" : "=l"(r) : "f"(v));
    return r;
}
__device__ __forceinline__ void fma2(unsigned long long& acc, unsigned long long a, unsigned long long b) {
    asm("fma.rn.f32x2 %0, %1, %2, %0;" : "+l"(acc) : "l"(a), "l"(b));
}
__device__ __forceinline__ void unpack2(unsigned long long p, float& lo, float& hi) {
    asm("mov.b64 {%0, %1}, %2;" : "=f"(lo), "=f"(hi) : "l"(p));
}

__global__ __launch_bounds__(256, 1)
void gemm128(const float* __restrict__ A, const float* __restrict__ B,
             const float* __restrict__ bias, const float* __restrict__ res,
             float* __restrict__ C, int M, int N, int K, int flags,
             long sA, long sB, long sC)
{
    A += blockIdx.z * sA; B += blockIdx.z * sB; C += blockIdx.z * sC;
    __shared__ float As[2][16][128];
    __shared__ float Bs[2][16][128];
    const int bm = blockIdx.y * 128;
    const int bn = blockIdx.x * 128;
    const int t = threadIdx.x;
    const int ty = t >> 4;
    const int tx = t & 15;

    unsigned long long acc2[8][4];
#pragma unroll
    for (int i = 0; i < 8; i++)
#pragma unroll
        for (int j = 0; j < 4; j++) acc2[i][j] = 0ull;

    const int tiles = K >> 4;
    const int a_row0 = t >> 2;
    const int a_kc = (t & 3) << 2;
    const int b_k0 = t >> 5;
    const int b_n4 = (t & 31) << 2;

    {
#pragma unroll
        for (int r = 0; r < 2; r++) {
            int row = a_row0 + r * 64;
            float4 v = *(const float4*)&A[(long)(bm + row) * K + a_kc];
            As[0][a_kc + 0][row] = v.x; As[0][a_kc + 1][row] = v.y;
            As[0][a_kc + 2][row] = v.z; As[0][a_kc + 3][row] = v.w;
        }
#pragma unroll
        for (int r = 0; r < 2; r++) {
            int k = b_k0 + r * 8;
            *(float4*)&Bs[0][k][b_n4] = *(const float4*)&B[(long)k * N + bn + b_n4];
        }
    }
    __syncthreads();

    for (int tt = 0; tt < tiles; tt++) {
        const int buf = tt & 1;
        float4 pa[2], pb[2];
        if (tt + 1 < tiles) {
            const int k0n = (tt + 1) << 4;
#pragma unroll
            for (int r = 0; r < 2; r++)
                pa[r] = *(const float4*)&A[(long)(bm + a_row0 + r * 64) * K + k0n + a_kc];
#pragma unroll
            for (int r = 0; r < 2; r++)
                pb[r] = *(const float4*)&B[(long)(k0n + b_k0 + r * 8) * N + bn + b_n4];
        }
#pragma unroll
        for (int k = 0; k < 16; k++) {
            float a[8];
            float4 a0 = *(const float4*)&As[buf][k][ty * 8];
            float4 a1 = *(const float4*)&As[buf][k][ty * 8 + 4];
            a[0] = a0.x; a[1] = a0.y; a[2] = a0.z; a[3] = a0.w;
            a[4] = a1.x; a[5] = a1.y; a[6] = a1.z; a[7] = a1.w;
            float4 b0 = *(const float4*)&Bs[buf][k][tx * 8];
            float4 b1 = *(const float4*)&Bs[buf][k][tx * 8 + 4];
            unsigned long long b2[4];
            b2[0] = pack2(b0.x, b0.y); b2[1] = pack2(b0.z, b0.w);
            b2[2] = pack2(b1.x, b1.y); b2[3] = pack2(b1.z, b1.w);
#pragma unroll
            for (int i = 0; i < 8; i++) {
                unsigned long long ad = dup2(a[i]);
#pragma unroll
                for (int j = 0; j < 4; j++) fma2(acc2[i][j], ad, b2[j]);
            }
        }
        if (tt + 1 < tiles) {
            const int nb = buf ^ 1;
#pragma unroll
            for (int r = 0; r < 2; r++) {
                int row = a_row0 + r * 64;
                As[nb][a_kc + 0][row] = pa[r].x; As[nb][a_kc + 1][row] = pa[r].y;
                As[nb][a_kc + 2][row] = pa[r].z; As[nb][a_kc + 3][row] = pa[r].w;
            }
#pragma unroll
            for (int r = 0; r < 2; r++)
                *(float4*)&Bs[nb][b_k0 + r * 8][b_n4] = pb[r];
        }
        __syncthreads();
    }

    const bool silu = (flags & FLAG_SILU) != 0;
#pragma unroll
    for (int i = 0; i < 8; i++) {
        const int m = bm + ty * 8 + i;
        float cv[8];
#pragma unroll
        for (int j = 0; j < 4; j++) unpack2(acc2[i][j], cv[2 * j], cv[2 * j + 1]);
        const long base = (long)m * N + bn + tx * 8;
#pragma unroll
        for (int j = 0; j < 8; j++) {
            float v = cv[j];
            if (bias) v += bias[bn + tx * 8 + j];
            if (silu) v = v / (1.0f + __expf(-v));
            if (res) v += res[base + j];
            cv[j] = v;
        }
        float4* cp = (float4*)&C[base];
        cp[0] = make_float4(cv[0], cv[1], cv[2], cv[3]);
        cp[1] = make_float4(cv[4], cv[5], cv[6], cv[7]);
    }
}

// ---------------- small weight-product kernel: We2 @ {Wvv, Wv, Wh1b} ----------------
__global__ void wprod_kernel(const float* __restrict__ We2, const float* __restrict__ Wv,
                             const float* __restrict__ Wvv, const float* __restrict__ Wh1,
                             float* __restrict__ MWv, float* __restrict__ W2v,
                             float* __restrict__ W2h)
{
    int l = blockIdx.z;
    int row = blockIdx.y;
    int n = threadIdx.x;
    __shared__ float a[HD];
    a[n] = We2[(long)l * HD * HD + row * HD + n];
    __syncthreads();
    const float* B;
    float* O;
    if (blockIdx.x == 0)      { B = Wvv + (long)l * HD * HD;                O = W2v; }
    else if (blockIdx.x == 1) { B = Wv + (long)l * HD * HD;                 O = MWv; }
    else                      { B = Wh1 + (long)l * 256 * HD + 128 * HD;    O = W2h; }
    float s = 0.0f;
#pragma unroll 8
    for (int k = 0; k < HD; k++) s += a[k] * B[k * HD + n];
    O[(long)l * HD * HD + row * HD + n] = s;
}

// ---------------- staging pack kernels (fp32) ----------------
__global__ void pack_We1cat_kernel(const float* __restrict__ We1, float* __restrict__ out)
{
    int idx = blockIdx.x * blockDim.x + threadIdx.x;
    if (idx >= 4 * HD * 256) return;
    int l = idx / (HD * 256);
    int rem = idx - l * HD * 256;
    int k = rem >> 8, n = rem & 255;
    const float* base = We1 + (long)l * 292 * HD;
    out[idx] = (n < HD) ? base[k * HD + n] : base[(HD + k) * HD + (n - HD)];
}
__global__ void pack_Wef_kernel(const float* __restrict__ We1, float* __restrict__ out)
{
    int idx = blockIdx.x * blockDim.x + threadIdx.x;
    if (idx >= 4 * EFK * HD) return;
    int l = idx / (EFK * HD);
    int rem = idx - l * EFK * HD;
    int k = rem >> 7, n = rem & 127;
    out[idx] = (k < EFR) ? We1[(long)l * 292 * HD + (256 + k) * HD + n] : 0.0f;
}
__global__ void pack_Wgv_kernel(const float* __restrict__ Wgv1, const float* __restrict__ Wgv2,
                                float* __restrict__ out)
{
    int idx = blockIdx.x * blockDim.x + threadIdx.x;
    if (idx >= HD * 256) return;
    int k = idx >> 8, n = idx & 255;
    out[idx] = (n < HD) ? Wgv1[k * HD + n] : Wgv2[k * HD + (n - HD)];
}
__global__ void bias_pre_kernel(const float* __restrict__ be2, const float* __restrict__ Wv,
                                const float* __restrict__ Wvv, const float* __restrict__ Wh1,
                                const float* __restrict__ bh1,
                                float* __restrict__ bWv, float* __restrict__ bWvv,
                                float* __restrict__ bh1adj)
{
    int l = blockIdx.x;
    int n = threadIdx.x;
    const float* b = be2 + l * HD;
    float s1 = 0.f, s2 = 0.f, s3 = 0.f;
    const float* w1 = Wv + (long)l * HD * HD;
    const float* w2 = Wvv + (long)l * HD * HD;
    const float* w3 = Wh1 + (long)l * 256 * HD + 128 * HD;
#pragma unroll 8
    for (int k = 0; k < HD; k++) {
        s1 += b[k] * w1[k * HD + n];
        s2 += b[k] * w2[k * HD + n];
        s3 += b[k] * w3[k * HD + n];
    }
    bWv[l * HD + n] = s1;
    bWvv[l * HD + n] = s2;
    bh1adj[l * HD + n] = bh1[l * HD + n] + 9.0f * s3;
}

// ---------------- single fused bf16 B-pack ----------------
#define NJOBS 13
struct PackJobs {
    const float* src[NJOBS];
    long sstride[NJOBS];
    long dstride[NJOBS];
    __nv_bfloat16* dst[NJOBS];
    int K[NJOBS];
    int N[NJOBS];
    int ldd[NJOBS];
    int coff[NJOBS];
    int layers[NJOBS];
    int srcN[NJOBS];   // src row width (>= N)
};
__global__ void pack_all_kernel(PackJobs J)
{
    int j = blockIdx.y;
    int l = blockIdx.z;
    if (l >= J.layers[j]) return;
    int idx = blockIdx.x * 256 + threadIdx.x;
    int KN = J.K[j] * J.N[j];
    if (idx >= KN) return;
    int k = idx / J.N[j], n = idx % J.N[j];
    float x = J.src[j][(long)l * J.sstride[j] + (long)k * J.srcN[j] + n];
    __nv_bfloat16 hi = __float2bfloat16(x);
    __nv_bfloat16 lo = __float2bfloat16(x - __bfloat162float(hi));
    __nv_bfloat16* d = J.dst[j] + (long)l * J.dstride[j] + (long)n * J.ldd[j] + J.coff[j];
    d[k] = hi;
    d[J.K[j] + k] = hi;
    d[2 * J.K[j] + k] = lo;
}

// ---------------- elementwise / reduction kernels ----------------
__global__ void edge_geom_kernel(const float* __restrict__ X, const float* __restrict__ edge_attr,
                                 const int* __restrict__ edges,
                                 float* __restrict__ unit, float* __restrict__ ef)
{
    int e = blockIdx.x * blockDim.x + threadIdx.x;
    if (e >= E_EDGES) return;
    int r = edges[e];
    int c = edges[E_EDGES + e];
    float dx = X[r * 3 + 0] - X[c * 3 + 0];
    float dy = X[r * 3 + 1] - X[c * 3 + 1];
    float dz = X[r * 3 + 2] - X[c * 3 + 2];
    float norm = sqrtf(dx * dx + dy * dy + dz * dz) + 1e-8f;
    float invn = 1.0f / norm;
    unit[e * 3 + 0] = dx * invn;
    unit[e * 3 + 1] = dy * invn;
    unit[e * 3 + 2] = dz * invn;
    const float PI_ = 3.14159265358979323846f;
    float cn = fminf(norm, 1.0f);
    float cut = 0.5f * (cosf(PI_ * cn) + 1.0f);
    float f = cut * invn;
#pragma unroll
    for (int j = 0; j < 20; j++)
        ef[(long)e * EFK + j] = sinf(norm * PI_ * (float)(j + 1)) * f;
#pragma unroll
    for (int j = 0; j < 16; j++)
        ef[(long)e * EFK + 20 + j] = edge_attr[e * 16 + j];
#pragma unroll
    for (int j = EFR; j < EFK; j++)
        ef[(long)e * EFK + j] = 0.0f;
}

__global__ void aggT_kernel(const __nv_bfloat16* __restrict__ t2, const float* __restrict__ unit,
                            __nv_bfloat16* __restrict__ aggdst, int aggld,
                            __nv_bfloat16* __restrict__ Mdst, float* __restrict__ usum)
{
    int n = blockIdx.x;
    int hh = threadIdx.x;
    float s = 0.f, mx = 0.f, my = 0.f, mz = 0.f;
#pragma unroll
    for (int j = 0; j < KEDGE; j++) {
        long e = (long)n * KEDGE + j;
        float tt = __bfloat162float(t2[e * 384 + hh]) + __bfloat162float(t2[e * 384 + 128 + hh]);
        float ux = unit[e * 3 + 0];
        float uy = unit[e * 3 + 1];
        float uz = unit[e * 3 + 2];
        s += tt; mx += tt * ux; my += tt * uy; mz += tt * uz;
    }
    wsplit1(aggdst + (long)n * aggld + hh, 128, s);
    wsplit1(Mdst + (long)(3 * n + 0) * 384 + hh, 128, mx);
    wsplit1(Mdst + (long)(3 * n + 1) * 384 + hh, 128, my);
    wsplit1(Mdst + (long)(3 * n + 2) * 384 + hh, 128, mz);
    if (hh < 3) {
        float u = 0.f;
#pragma unroll
        for (int j = 0; j < KEDGE; j++) u += unit[((long)n * KEDGE + j) * 3 + hh];
        usum[n * 3 + hh] = u;
    }
}

__global__ void vupdate_kernel(const float* __restrict__ vin, float* __restrict__ vout,
                               const float* __restrict__ mvv, const float* __restrict__ vagg,
                               const float* __restrict__ usum, const float* __restrict__ bWv,
                               const int* __restrict__ edges)
{
    int n = blockIdx.x;
    int hh = threadIdx.x;
    float bw = bWv[hh];
    float a0 = vagg[(long)n * 384 + hh]       + usum[n * 3 + 0] * bw;
    float a1 = vagg[(long)n * 384 + 128 + hh] + usum[n * 3 + 1] * bw;
    float a2 = vagg[(long)n * 384 + 256 + hh] + usum[n * 3 + 2] * bw;
    if (vin) {
        a0 += vin[(long)n * 384 + hh];
        a1 += vin[(long)n * 384 + 128 + hh];
        a2 += vin[(long)n * 384 + 256 + hh];
#pragma unroll
        for (int j = 0; j < KEDGE; j++) {
            long e = (long)n * KEDGE + j;
            int c = edges[E_EDGES + e];
            float b = mvv[e * HD + hh];
            a0 += b * vin[(long)c * 384 + hh];
            a1 += b * vin[(long)c * 384 + 128 + hh];
            a2 += b * vin[(long)c * 384 + 256 + hh];
        }
    }
    vout[(long)n * 384 + hh] = a0;
    vout[(long)n * 384 + 128 + hh] = a1;
    vout[(long)n * 384 + 256 + hh] = a2;
}

__global__ void meanh1_kernel(const float* __restrict__ hintra, float* __restrict__ part)
{
    int s = blockIdx.x;
    int c = blockIdx.y;
    int k = threadIdx.x;
    float acc = 0.0f;
    const float* p = hintra + ((long)s * SEGSZ + c * 64) * HD + k;
#pragma unroll 8
    for (int u = 0; u < 64; u++) acc += p[u * HD];
    part[(s * 8 + c) * HD + k] = acc;
}

// attn: reads 8-way partials of opposite segment directly (meanh2 fused)
__global__ void attn_kernel(const float* __restrict__ hintra, const float* __restrict__ part,
                            float* __restrict__ w)
{
    int s = blockIdx.x;
    int t = threadIdx.x;
    __shared__ float sm[HD];
    __shared__ float red[SEGSZ];
    int opp = s ^ 1;
    if (t < HD) {
        float a = 0.0f;
#pragma unroll
        for (int c = 0; c < 8; c++) a += part[(opp * 8 + c) * HD + t];
        sm[t] = a * (1.0f / (float)SEGSZ);
    }
    __syncthreads();
    int node = s * SEGSZ + t;
    const float* hr = hintra + (long)node * HD;
    float sc = 0.0f;
#pragma unroll 8
    for (int k = 0; k < HD; k++) sc += hr[k] * sm[k];
    red[t] = sc;
    __syncthreads();
    for (int st = SEGSZ / 2; st > 0; st >>= 1) {
        if (t < st) red[t] = fmaxf(red[t], red[t + st]);
        __syncthreads();
    }
    float mx = red[0];
    __syncthreads();
    float ex = expf(sc - mx);
    red[t] = ex;
    __syncthreads();
    for (int st = SEGSZ / 2; st > 0; st >>= 1) {
        if (t < st) red[t] += red[t + st];
        __syncthreads();
    }
    w[node] = ex / red[0];
}

__global__ void v2n_kernel(const float* __restrict__ vp, float* __restrict__ v2n)
{
    int idx = blockIdx.x * blockDim.x + threadIdx.x;
    if (idx >= N_NODES * HD) return;
    int n = idx / HD;
    int k = idx % HD;
    float a = vp[(long)(n * 3 + 0) * 256 + HD + k];
    float b = vp[(long)(n * 3 + 1) * 256 + HD + k];
    float c = vp[(long)(n * 3 + 2) * 256 + HD + k];
    v2n[idx] = sqrtf(a * a + b * b + c * c + 1e-8f);
}

__global__ void pv_kernel(const float* __restrict__ vp, const float* __restrict__ mix,
                          const float* __restrict__ Wf, float* __restrict__ pv)
{
    int n = blockIdx.x;
    int k = threadIdx.x;
    __shared__ float sd[3][HD];
    float hf = mix[(long)n * 256 + k];
    float bg = mix[(long)n * 256 + HD + k];
    float s = hf * bg;
    sd[0][k] = vp[(long)(n * 3 + 0) * 256 + k] * s;
    sd[1][k] = vp[(long)(n * 3 + 1) * 256 + k] * s;
    sd[2][k] = vp[(long)(n * 3 + 2) * 256 + k] * s;
    __syncthreads();
    if (k < 27) {
        int o = k / 3, c = k % 3;
        float acc = 0.0f;
#pragma unroll 8
        for (int kk = 0; kk < HD; kk++) acc += sd[c][kk] * Wf[kk * 9 + o];
        pv[(long)n * 27 + k] = acc;
    }
}

__global__ void predsum_kernel(const float* __restrict__ pv, float* __restrict__ pred)
{
    int s = blockIdx.x;
    int j = threadIdx.x;
    if (j >= 27) return;
    float acc = 0.0f;
    for (int u = 0; u < SEGSZ; u++)
        acc += pv[(long)(s * SEGSZ + u) * 27 + j];
    pred[s * 27 + j] = acc;
}

__global__ void final_kernel(const float* __restrict__ pred, float* __restrict__ out)
{
    int s = threadIdx.x;
    if (s >= NSEG) return;
    const float* p = pred + s * 27;
#pragma unroll
    for (int r = 0; r < 3; r++) {
#pragma unroll
        for (int c = 0; c < 3; c++) {
            float A = p[0 * 3 + r] * p[1 * 3 + c]
                    + p[3 * 3 + r] * p[2 * 3 + c]
                    + p[4 * 3 + r] * p[5 * 3 + c]
                    + p[7 * 3 + r] * p[6 * 3 + c];
            out[s * 12 + r * 4 + c] = A * 100.0f;
        }
        out[s * 12 + r * 4 + 3] = p[8 * 3 + r] * 10.0f;
    }
}

// ---------------- host driver ----------------
static void launch_tc(const __nv_bfloat16* A2, int lda, int Ktot, const __nv_bfloat16* B2,
                      const float* bias, const float* res, float* C, int M, int Nt, int flags,
                      __nv_bfloat16* sdst = nullptr, int sldd = 0,
                      const int* edges = nullptr, const float* ArAc = nullptr,
                      int bmtile = 128, cudaStream_t st = 0)
{
    if (bmtile == 64) {
        dim3 grid(Nt / 128, M / 64);
        tcgemm<64><<<grid, 256, TCSMEM64, st>>>(A2, lda, Ktot, B2, bias, res, C, Nt, flags,
                                                sdst, sldd, edges, ArAc);
    } else {
        dim3 grid(Nt / 128, M / 128);
        tcgemm<128><<<grid, 256, TCSMEM128, st>>>(A2, lda, Ktot, B2, bias, res, C, Nt, flags,
                                                  sdst, sldd, edges, ArAc);
    }
}

static void launch_gemm(const float* A, const float* B, const float* bias,
                        const float* res, float* C, int M, int N, int K, int flags,
                        int batch = 1, long sA = 0, long sB = 0, long sC = 0)
{
    dim3 grid(N / 128, M / 128, batch);
    gemm128<<<grid, 256>>>(A, B, bias, res, C, M, N, K, flags, sA, sB, sC);
}

static void launch_split(const float* src, int srcld, int M, int K,
                         __nv_bfloat16* dst, int ldd, int coff, const float* rowscale)
{
    long total = (long)M * K;
    splitA_kernel<<<(int)((total + 255) / 256), 256>>>(src, srcld, K, dst, ldd, coff,
                                                       rowscale, total);
}

template <typename T>
static T* sym(const void* s)
{
    void* p = nullptr;
    cudaGetSymbolAddress(&p, s);
    return (T*)p;
}

extern "C" void kernel_launch(void* const* d_in, const int* in_sizes, int n_in,
                              void* d_out, int out_size)
{
    const float* X        = (const float*)d_in[0];
    const float* node_attr= (const float*)d_in[1];
    const float* edge_attr= (const float*)d_in[2];
    const float* W_in1    = (const float*)d_in[3];
    const float* b_in1    = (const float*)d_in[4];
    const float* W_in2    = (const float*)d_in[5];
    const float* b_in2    = (const float*)d_in[6];
    const float* We1      = (const float*)d_in[7];
    const float* be1      = (const float*)d_in[8];
    const float* We2      = (const float*)d_in[9];
    const float* be2      = (const float*)d_in[10];
    const float* Wv       = (const float*)d_in[11];
    const float* Wvv      = (const float*)d_in[12];
    const float* Wh1      = (const float*)d_in[13];
    const float* bh1      = (const float*)d_in[14];
    const float* Wh2      = (const float*)d_in[15];
    const float* bh2      = (const float*)d_in[16];
    const float* Wi1      = (const float*)d_in[17];
    const float* bi1      = (const float*)d_in[18];
    const float* Wi2      = (const float*)d_in[19];
    const float* bi2      = (const float*)d_in[20];
    const float* Wgv1     = (const float*)d_in[21];
    const float* Wgv2     = (const float*)d_in[22];
    const float* Wg1      = (const float*)d_in[23];
    const float* bg1      = (const float*)d_in[24];
    const float* Wg2      = (const float*)d_in[25];
    const float* bg2      = (const float*)d_in[26];
    const float* Wf       = (const float*)d_in[27];
    const int*   edges    = (const int*)d_in[28];
    float* out = (float*)d_out;

    static bool attr_done = false;
    static cudaStream_t s2;
    static cudaEvent_t evT, evAgg, evV, evPack, evFork;
    if (!attr_done) {
        cudaFuncSetAttribute(tcgemm<128>, cudaFuncAttributeMaxDynamicSharedMemorySize, TCSMEM128);
        cudaFuncSetAttribute(tcgemm<64>, cudaFuncAttributeMaxDynamicSharedMemorySize, TCSMEM64);
        cudaStreamCreateWithFlags(&s2, cudaStreamNonBlocking);
        cudaEventCreateWithFlags(&evT, cudaEventDisableTiming);
        cudaEventCreateWithFlags(&evAgg, cudaEventDisableTiming);
        cudaEventCreateWithFlags(&evV, cudaEventDisableTiming);
        cudaEventCreateWithFlags(&evPack, cudaEventDisableTiming);
        cudaEventCreateWithFlags(&evFork, cudaEventDisableTiming);
        attr_done = true;
    }

    float* p_t0     = sym<float>(g_t0);
    float* p_h      = sym<float>(g_h);
    float* p_ArAc   = sym<float>(g_ArAc);
    float* p_hintra = sym<float>(g_hintra);
    float* p_v2n    = sym<float>(g_v2n);
    float* p_mix    = sym<float>(g_mix);
    float* p_ef     = sym<float>(g_ef);
    float* p_mvv    = sym<float>(g_mvv);
    float* p_unit   = sym<float>(g_unit);
    float* p_usum   = sym<float>(g_usum);
    float* p_va     = sym<float>(g_va);
    float* p_vb     = sym<float>(g_vb);
    float* p_vagg   = sym<float>(g_vagg);
    float* p_vp     = sym<float>(g_vp);
    float* p_w      = sym<float>(g_w);
    float* p_meanp  = sym<float>(g_meanp);
    float* p_pv     = sym<float>(g_pv);
    float* p_pred   = sym<float>(g_pred);
    float* p_We1cat = sym<float>(g_We1cat);
    float* p_Wef    = sym<float>(g_Wef);
    float* p_W2v    = sym<float>(g_W2v);
    float* p_MWv    = sym<float>(g_MWv);
    float* p_W2h    = sym<float>(g_W2h);
    float* p_Wgvcat = sym<float>(g_Wgvcat);
    float* p_bWv    = sym<float>(g_bWv);
    float* p_bWvv   = sym<float>(g_bWvv);
    float* p_bh1adj = sym<float>(g_bh1adj);

    __nv_bfloat16* pa_cat = sym<__nv_bfloat16>(a2_cat);
    __nv_bfloat16* pa_u   = sym<__nv_bfloat16>(a2_u);
    __nv_bfloat16* pa_x   = sym<__nv_bfloat16>(a2_x);
    __nv_bfloat16* pa_t   = sym<__nv_bfloat16>(a2_t);
    __nv_bfloat16* pa_ef  = sym<__nv_bfloat16>(a2_ef);
    __nv_bfloat16* pa_M   = sym<__nv_bfloat16>(a2_M);
    __nv_bfloat16* pb_We1 = sym<__nv_bfloat16>(b2_We1cat);
    __nv_bfloat16* pb_Wef = sym<__nv_bfloat16>(b2_Wef);
    __nv_bfloat16* pb_W2v = sym<__nv_bfloat16>(b2_W2v);
    __nv_bfloat16* pb_MWv = sym<__nv_bfloat16>(b2_MWv);
    __nv_bfloat16* pb_Wh1 = sym<__nv_bfloat16>(b2_Wh1);
    __nv_bfloat16* pb_Wh2 = sym<__nv_bfloat16>(b2_Wh2);
    __nv_bfloat16* pb_Wi1 = sym<__nv_bfloat16>(b2_Wi1);
    __nv_bfloat16* pb_Wi2 = sym<__nv_bfloat16>(b2_Wi2);
    __nv_bfloat16* pb_Wgv = sym<__nv_bfloat16>(b2_Wgv);
    __nv_bfloat16* pb_Wg1 = sym<__nv_bfloat16>(b2_Wg1);
    __nv_bfloat16* pb_Wg2 = sym<__nv_bfloat16>(b2_Wg2);

    // ---- fork s2 from main (required for stream capture) ----
    cudaEventRecord(evFork, 0);
    cudaStreamWaitEvent(s2, evFork, 0);

    // ---- s2: entire weight pipeline (independent of activation pipeline) ----
    pack_We1cat_kernel<<<(4 * HD * 256 + 255) / 256, 256, 0, s2>>>(We1, p_We1cat);
    pack_Wef_kernel<<<(4 * EFK * HD + 255) / 256, 256, 0, s2>>>(We1, p_Wef);
    pack_Wgv_kernel<<<(HD * 256 + 255) / 256, 256, 0, s2>>>(Wgv1, Wgv2, p_Wgvcat);
    {
        dim3 g(3, HD, 4);
        wprod_kernel<<<g, HD, 0, s2>>>(We2, Wv, Wvv, Wh1, p_MWv, p_W2v, p_W2h);
    }
    bias_pre_kernel<<<4, HD, 0, s2>>>(be2, Wv, Wvv, Wh1, bh1, p_bWv, p_bWvv, p_bh1adj);
    {
        PackJobs J;
        auto set = [&](int j, const float* src, long ss, int K, int N,
                       __nv_bfloat16* dst, long ds, int ldd, int coff, int layers,
                       int srcN) {
            J.src[j] = src; J.sstride[j] = ss; J.K[j] = K; J.N[j] = N;
            J.dst[j] = dst; J.dstride[j] = ds; J.ldd[j] = ldd; J.coff[j] = coff;
            J.layers[j] = layers; J.srcN[j] = srcN;
        };
        set(0,  p_We1cat, (long)HD * 256, 128, 256, pb_We1, (long)256 * 384, 384, 0, 4, 256);
        set(1,  p_Wef, (long)EFK * HD, EFR, 128, pb_Wef, (long)128 * 128, 128, 0, 4, 128);
        set(2,  p_W2v, (long)HD * HD, 128, 128, pb_W2v, (long)128 * 384, 384, 0, 4, 128);
        set(3,  p_MWv, (long)HD * HD, 128, 128, pb_MWv, (long)128 * 384, 384, 0, 4, 128);
        set(4,  p_W2h, (long)HD * HD, 128, 128, pb_Wh1, (long)128 * 768, 768, 384, 4, 128);
        set(5,  Wh1, (long)256 * HD, 128, 128, pb_Wh1, (long)128 * 768, 768, 0, 4, 128);
        set(6,  Wh2, (long)HD * HD, 128, 128, pb_Wh2, (long)128 * 384, 384, 0, 4, 128);
        set(7,  Wi1, (long)HD * HD, 128, 128, pb_Wi1, (long)128 * 384, 384, 0, 4, 128);
        set(8,  Wi2, (long)HD * HD, 128, 128, pb_Wi2, (long)128 * 384, 384, 0, 4, 128);
        set(9,  p_Wgvcat, 0, 128, 256, pb_Wgv, 0, 384, 0, 1, 256);
        set(10, Wg1, 0, 128, 128, pb_Wg1, 0, 768, 0, 1, 128);
        set(11, Wg1 + 128 * HD, 0, 128, 128, pb_Wg1, 0, 768, 384, 1, 128);
        set(12, Wg2, 0, 128, 256, pb_Wg2, 0, 384, 0, 1, 256);
        dim3 grid(128, NJOBS, 4);
        pack_all_kernel<<<grid, 256, 0, s2>>>(J);
    }
    cudaEventRecord(evPack, s2);

    // ---- main: activation pipeline (overlaps the weight pipeline) ----
    edge_geom_kernel<<<(E_EDGES + 255) / 256, 256>>>(X, edge_attr, edges, p_unit, p_ef);
    launch_split(p_ef, EFK, E_EDGES, EFR, pa_ef, 128, 0, nullptr);

    // h = silu(node_attr @ W_in1 + b_in1) @ W_in2 + b_in2  (fp32 — no packed weights needed)
    launch_gemm(node_attr, W_in1, b_in1, nullptr, p_t0, N_NODES, HD, 64, FLAG_SILU);
    launch_gemm(p_t0, W_in2, b_in2, nullptr, p_h, N_NODES, HD, HD, 0);
    launch_split(p_h, HD, N_NODES, HD, pa_cat, 768, 0, nullptr);

    // join: packed weights must be ready before first consumer
    cudaStreamWaitEvent(0, evPack, 0);

    float* vin = nullptr;
    float* vbuf0 = p_va;
    float* vbuf1 = p_vb;

    for (int i = 0; i < 4; i++) {
        const float* be1_i = be1 + i * HD;
        const float* bh2_i = bh2 + i * HD;
        const float* bi1_i = bi1 + i * HD;
        const float* bi2_i = bi2 + i * HD;
        float* vout = (i & 1) ? vbuf1 : vbuf0;

        // [Ar|Ac] = h @ [W_r|W_c]
        launch_tc(pa_cat, 768, 384, pb_We1 + (long)i * 256 * 384,
                  nullptr, nullptr, p_ArAc, N_NODES, 256, 0);

        // protect pa_t / pa_M / p_usum: previous layer's v-chain must be done
        if (i > 0) cudaStreamWaitEvent(0, evV, 0);

        // t = silu(ef@Wef + be1 + Ar[row] + Ac[col]) -> split pa_t   (K=128)
        launch_tc(pa_ef, 128, 128, pb_Wef + (long)i * 128 * 128,
                  be1_i, nullptr, nullptr, E_EDGES, 128, FLAG_SILU | FLAG_COMBINE,
                  pa_t, 384, edges, p_ArAc);
        cudaEventRecord(evT, 0);

        // ---- v-chain forked to s2 ----
        cudaStreamWaitEvent(s2, evT, 0);
        if (i > 0)
            launch_tc(pa_t, 384, 384, pb_W2v + (long)i * 128 * 384,
                      p_bWvv + i * HD, nullptr, p_mvv, E_EDGES, 128, 0,
                      nullptr, 0, nullptr, nullptr, 128, s2);

        // aggregate t (main)
        aggT_kernel<<<N_NODES, HD>>>(pa_t, p_unit, pa_cat + 384, 768, pa_M, p_usum);
        cudaEventRecord(evAgg, 0);

        // s2: vagg = Mt @ (We2@Wv), then vupdate
        cudaStreamWaitEvent(s2, evAgg, 0);
        launch_tc(pa_M, 384, 384, pb_MWv + (long)i * 128 * 384,
                  nullptr, nullptr, p_vagg, 3 * N_NODES, 128, 0,
                  nullptr, 0, nullptr, nullptr, 128, s2);
        vupdate_kernel<<<N_NODES, HD, 0, s2>>>(vin, vout, p_mvv, p_vagg, p_usum,
                                               p_bWv + i * HD, edges);
        cudaEventRecord(evV, s2);

        // ---- h-chain on main ----
        launch_tc(pa_cat, 768, 768, pb_Wh1 + (long)i * 128 * 768,
                  p_bh1adj + i * HD, nullptr, nullptr, N_NODES, 128, FLAG_SILU, pa_u, 384,
                  nullptr, nullptr, 64);
        launch_tc(pa_u, 384, 384, pb_Wh2 + (long)i * 128 * 384,
                  bh2_i, p_h, p_hintra, N_NODES, 128, 0, nullptr, 0,
                  nullptr, nullptr, 64);

        // segment attention (meanh2 fused into attn)
        {
            dim3 g1(NSEG, 8);
            meanh1_kernel<<<g1, HD>>>(p_hintra, p_meanp);
        }
        attn_kernel<<<NSEG, SEGSZ>>>(p_hintra, p_meanp, p_w);
        launch_split(p_hintra, HD, N_NODES, HD, pa_x, 384, 0, p_w);
        launch_tc(pa_x, 384, 384, pb_Wi1 + (long)i * 128 * 384,
                  bi1_i, nullptr, nullptr, N_NODES, 128, FLAG_SILU, pa_u, 384,
                  nullptr, nullptr, 64);
        launch_tc(pa_u, 384, 384, pb_Wi2 + (long)i * 128 * 384,
                  bi2_i, p_hintra, p_h, N_NODES, 128, 0, pa_cat, 768,
                  nullptr, nullptr, 64);

        vin = vout;
    }

    // join v-chain before final v projection
    cudaStreamWaitEvent(0, evV, 0);

    // [v1 | v2] = v @ [Wgv1 | Wgv2]
    launch_split(vin, HD, 3 * N_NODES, HD, pa_M, 384, 0, nullptr);
    launch_tc(pa_M, 384, 384, pb_Wgv, nullptr, nullptr, p_vp, 3 * N_NODES, 256, 0);
    v2n_kernel<<<(N_NODES * HD + 255) / 256, 256>>>(p_vp, p_v2n);

    // mix = silu([h|v2n] @ Wg1 + bg1) @ Wg2 + bg2
    launch_split(p_v2n, HD, N_NODES, HD, pa_cat, 768, 384, nullptr);
    launch_tc(pa_cat, 768, 768, pb_Wg1, bg1, nullptr, nullptr, N_NODES, 128, FLAG_SILU,
              pa_u, 384, nullptr, nullptr, 64);
    launch_tc(pa_u, 384, 384, pb_Wg2, bg2, nullptr, p_mix, N_NODES, 256, 0,
              nullptr, 0, nullptr, nullptr, 64);

    // epilogue
    pv_kernel<<<N_NODES, HD>>>(p_vp, p_mix, Wf, p_pv);
    predsum_kernel<<<NSEG, 32>>>(p_pv, p_pred);
    final_kernel<<<1, 32>>>(p_pred, out);
}